// round 13
// baseline (speedup 1.0000x reference)
#include <cuda_runtime.h>
#include <cuda_bf16.h>
#include <cuda_fp16.h>
#include <math.h>
#include <stdint.h>

#define B_ 8
#define C_ 1024
#define T_ 2048
#define I_ 512
#define BN_EPS 1e-5f

typedef __nv_bfloat16 bf16;

// ================= static scratch =================
__device__ __align__(16) bf16   g_xTh[B_ * T_ * C_];
__device__ __align__(16) bf16   g_xTl[B_ * T_ * C_];
__device__ __align__(16) __half g_xT16[B_ * T_ * C_];
__device__ __align__(16) __half g_wg16[I_ * C_];
__device__ __align__(16) bf16   g_wth[I_ * C_],  g_wtl[I_ * C_];
__device__ __align__(16) bf16   g_wph[I_ * C_],  g_wpl[I_ * C_];
__device__ __align__(16) __half g_W16[C_ * I_];
__device__ __align__(16) __half g_g16[B_ * I_ * T_];
__device__ __align__(16) bf16   g_thh[B_ * T_ * I_], g_thl[B_ * T_ * I_];
__device__ __align__(16) bf16   g_phh[B_ * T_ * I_], g_phl[B_ * T_ * I_];
__device__ __align__(16) float  g_f[33554432];            // [B,T,S] fp32
__device__ __align__(16) __half g_E[33554432];            // fp16 attention
__device__ __align__(16) __half g_yT16[B_ * T_ * I_];
__device__ float g_mean[C_], g_rstd[C_];

// ================= PTX helpers (baseline features only) =================
#define LDSM4(r, a) \
    asm volatile("ldmatrix.sync.aligned.m8n8.x4.shared.b16 {%0,%1,%2,%3}, [%4];" \
        : "=r"((r)[0]), "=r"((r)[1]), "=r"((r)[2]), "=r"((r)[3]) : "r"(a))

#define MMA_BF16(c, a, b) \
    asm volatile("mma.sync.aligned.m16n8k16.row.col.f32.bf16.bf16.f32 " \
        "{%0,%1,%2,%3}, {%4,%5,%6,%7}, {%8,%9}, {%0,%1,%2,%3};" \
        : "+f"((c)[0]), "+f"((c)[1]), "+f"((c)[2]), "+f"((c)[3]) \
        : "r"((a)[0]), "r"((a)[1]), "r"((a)[2]), "r"((a)[3]), \
          "r"((b)[0]), "r"((b)[1]))

#define MMA_F16(c, a, b) \
    asm volatile("mma.sync.aligned.m16n8k16.row.col.f32.f16.f16.f32 " \
        "{%0,%1,%2,%3}, {%4,%5,%6,%7}, {%8,%9}, {%0,%1,%2,%3};" \
        : "+f"((c)[0]), "+f"((c)[1]), "+f"((c)[2]), "+f"((c)[3]) \
        : "r"((a)[0]), "r"((a)[1]), "r"((a)[2]), "r"((a)[3]), \
          "r"((b)[0]), "r"((b)[1]))

#define CP_ASYNC16(saddr, gptr) \
    asm volatile("cp.async.cg.shared.global [%0], [%1], 16;" \
        :: "r"(saddr), "l"(__cvta_generic_to_global(gptr)))
#define CP_COMMIT() asm volatile("cp.async.commit_group;" ::: "memory")

// ================= GEMM tile body: 128x128 ======================
// D[m,n] = sum_k A[m,k]*B[n,k].  K-major rows, 16-bit elements.
// MODE 0 (FULL3): comps [Ah,Al,Bh,Bl], 3 products, K-chunk 16, 4-stage (96KB)
// MODE 2 (SGL)  : comps [A,B],         1 product,  K-chunk 32, 4-stage (80KB)
// EPI: 0 fp32 | 2 bf16 split+bias[n] | 3 fp32+bias[m]+resid
//      6 f16 single+bias[m] | 7 f16 single

template <int EPI, int MODE, bool F16>
__device__ __forceinline__ void gemm_tile(
    const bf16* __restrict__ Ah, const bf16* __restrict__ Al,
    const bf16* __restrict__ Bh, const bf16* __restrict__ Bl,
    float* __restrict__ Cf, void* __restrict__ Coh, void* __restrict__ Col,
    const float* __restrict__ bias, const float* __restrict__ resid,
    int K, int ldc, long long sA, long long sB, long long sC, long long sR,
    int bm0, int bn0, int z, char* sm)
{
    constexpr int NCOMP  = (MODE == 0) ? 4 : 2;
    constexpr int BC     = (MODE == 0) ? 2 : 1;
    constexpr int KCH    = (MODE == 0) ? 16 : 32;   // K per chunk
    constexpr int RB     = (MODE == 0) ? 48 : 80;   // padded row bytes
    constexpr int CB     = 128 * RB;                // component bytes
    constexpr int NSTAGE = 4;
    constexpr int BUFB   = NCOMP * CB;
    constexpr int UPC    = 128 * (KCH / 8);         // 16B units per component
    constexpr int NS     = KCH / 16;                // k16 steps per chunk

    const uint32_t sbase = (uint32_t)__cvta_generic_to_shared(sm);
    const int tid = threadIdx.x;
    const int lane = tid & 31;
    const int wid = tid >> 5;
    const int wm = (wid >> 1) * 32;
    const int wn = (wid & 1) * 64;

    const bf16* gp[NCOMP];
    gp[0] = Ah + sA * z + (long long)bm0 * K;
    if (MODE == 0) {
        gp[1] = Al + sA * z + (long long)bm0 * K;
        gp[2] = Bh + sB * z + (long long)bn0 * K;
        gp[3] = Bl + sB * z + (long long)bn0 * K;
    } else {
        gp[1] = Bh + sB * z + (long long)bn0 * K;
    }

    float acc[2][8][4];
#pragma unroll
    for (int i = 0; i < 2; i++)
#pragma unroll
        for (int j = 0; j < 8; j++)
#pragma unroll
            for (int q = 0; q < 4; q++) acc[i][j][q] = 0.0f;

    auto load_chunk = [&](int k0, int buf) {
        const uint32_t b = sbase + buf * BUFB;
#pragma unroll
        for (int i = 0; i < (NCOMP * UPC) / 256; i++) {
            const int u = tid + i * 256;
            const int comp = u / UPC;
            const int rem = u % UPC;
            const int row = rem / (KCH / 8);
            const int un = rem % (KCH / 8);
            const bf16* g = gp[comp] + (long long)row * K + k0 + un * 8;
            const uint32_t s = b + comp * CB + row * RB + un * 16;
            CP_ASYNC16(s, g);
        }
        CP_COMMIT();
    };

    auto compute = [&](int buf) {
        const uint32_t b = sbase + buf * BUFB;
        const uint32_t arow = wm + (lane & 15);
        const uint32_t akoff = ((lane >> 4) & 1) * 16;
        const uint32_t brow = wn + ((lane >> 4) << 3) + (lane & 7);
        const uint32_t bkoff = ((lane >> 3) & 1) * 16;
#pragma unroll
        for (int s = 0; s < NS; s++) {
            uint32_t ah[2][4], al[2][4];
#pragma unroll
            for (int mt = 0; mt < 2; mt++) {
                const uint32_t addr = b + (arow + mt * 16) * RB + s * 32 + akoff;
                LDSM4(ah[mt], addr);
                if (MODE == 0) LDSM4(al[mt], addr + CB);
            }
            const uint32_t bbase = b + BC * CB + brow * RB + s * 32 + bkoff;
            uint32_t rh[2][4], rl[2][4];
            LDSM4(rh[0], bbase);
            if (MODE == 0) LDSM4(rl[0], bbase + CB);
#pragma unroll
            for (int np = 0; np < 4; np++) {
                const int cur = np & 1;
                if (np < 3) {
                    const uint32_t na = bbase + (np + 1) * 16 * RB;
                    LDSM4(rh[cur ^ 1], na);
                    if (MODE == 0) LDSM4(rl[cur ^ 1], na + CB);
                }
                const int nb = np * 2;
                uint32_t b0[2] = { rh[cur][0], rh[cur][1] };
                uint32_t b1[2] = { rh[cur][2], rh[cur][3] };
                if (F16) {
                    MMA_F16(acc[0][nb],     ah[0], b0);
                    MMA_F16(acc[1][nb],     ah[1], b0);
                    MMA_F16(acc[0][nb + 1], ah[0], b1);
                    MMA_F16(acc[1][nb + 1], ah[1], b1);
                } else {
                    MMA_BF16(acc[0][nb],     ah[0], b0);
                    MMA_BF16(acc[1][nb],     ah[1], b0);
                    MMA_BF16(acc[0][nb + 1], ah[0], b1);
                    MMA_BF16(acc[1][nb + 1], ah[1], b1);
                }
                if (MODE == 0) {
                    uint32_t c0[2] = { rl[cur][0], rl[cur][1] };
                    uint32_t c1[2] = { rl[cur][2], rl[cur][3] };
                    MMA_BF16(acc[0][nb],     ah[0], c0);
                    MMA_BF16(acc[1][nb],     ah[1], c0);
                    MMA_BF16(acc[0][nb + 1], ah[0], c1);
                    MMA_BF16(acc[1][nb + 1], ah[1], c1);
                    MMA_BF16(acc[0][nb],     al[0], b0);
                    MMA_BF16(acc[1][nb],     al[1], b0);
                    MMA_BF16(acc[0][nb + 1], al[0], b1);
                    MMA_BF16(acc[1][nb + 1], al[1], b1);
                }
            }
        }
    };

    const int nch = K / KCH;
#pragma unroll
    for (int p = 0; p < NSTAGE - 1; p++)
        load_chunk(p * KCH, p);

    for (int c = 0; c < nch; c++) {
        asm volatile("cp.async.wait_group %0;" :: "n"(NSTAGE - 2) : "memory");
        __syncthreads();
        const int nxt = c + NSTAGE - 1;
        if (nxt < nch) load_chunk(nxt * KCH, nxt % NSTAGE);
        compute(c % NSTAGE);
    }

    // ---- epilogue ----
    const int r0 = lane >> 2;
    const int cq = (lane & 3) * 2;
#pragma unroll
    for (int mt = 0; mt < 2; mt++) {
        const int mA = bm0 + wm + mt * 16 + r0;
        const int mB = mA + 8;
        float biasA = 0.0f, biasB = 0.0f;
        if (EPI == 3 || EPI == 6) { biasA = bias[mA]; biasB = bias[mB]; }
        const long long rowA = sC * z + (long long)mA * ldc;
        const long long rowB = sC * z + (long long)mB * ldc;
#pragma unroll
        for (int nt = 0; nt < 8; nt++) {
            const int n = bn0 + wn + nt * 8 + cq;
            float v0 = acc[mt][nt][0], v1 = acc[mt][nt][1];
            float v2 = acc[mt][nt][2], v3 = acc[mt][nt][3];
            if (EPI == 2) {
                const float bn0v = bias[n], bn1v = bias[n + 1];
                v0 += bn0v; v1 += bn1v; v2 += bn0v; v3 += bn1v;
            }
            if (EPI == 3 || EPI == 6) { v0 += biasA; v1 += biasA; v2 += biasB; v3 += biasB; }
            if (EPI == 0 || EPI == 3) {
                if (EPI == 3) {
                    const long long rA = sR * z + (long long)mA * ldc + n;
                    const long long rB = sR * z + (long long)mB * ldc + n;
                    float2 ra = *(const float2*)(resid + rA);
                    float2 rb = *(const float2*)(resid + rB);
                    v0 += ra.x; v1 += ra.y; v2 += rb.x; v3 += rb.y;
                }
                *(float2*)(Cf + rowA + n) = make_float2(v0, v1);
                *(float2*)(Cf + rowB + n) = make_float2(v2, v3);
            } else if (EPI == 6 || EPI == 7) {
                *(__half2*)((__half*)Coh + rowA + n) = __floats2half2_rn(v0, v1);
                *(__half2*)((__half*)Coh + rowB + n) = __floats2half2_rn(v2, v3);
            } else {
                __nv_bfloat162 hA = __floats2bfloat162_rn(v0, v1);
                __nv_bfloat162 hB = __floats2bfloat162_rn(v2, v3);
                __nv_bfloat162 lA = __floats2bfloat162_rn(
                    v0 - __bfloat162float(hA.x), v1 - __bfloat162float(hA.y));
                __nv_bfloat162 lB = __floats2bfloat162_rn(
                    v2 - __bfloat162float(hB.x), v3 - __bfloat162float(hB.y));
                *(__nv_bfloat162*)((bf16*)Coh + rowA + n) = hA;
                *(__nv_bfloat162*)((bf16*)Coh + rowB + n) = hB;
                *(__nv_bfloat162*)((bf16*)Col + rowA + n) = lA;
                *(__nv_bfloat162*)((bf16*)Col + rowB + n) = lB;
            }
        }
    }
}

// smem sizes
#define SM_FULL3 (4 * 4 * 128 * 48)   // 98304: 4 stages x 4 comps x 6144
#define SM_SGL   (4 * 2 * 128 * 80)   // 81920: 4 stages x 2 comps x 10240

// ---- plain wrapper (3D grid, one tile per CTA) ----
template <int EPI, int MODE, bool F16>
__global__ __launch_bounds__(256, 2)
void mma_gemm(const bf16* __restrict__ Ah, const bf16* __restrict__ Al,
              const bf16* __restrict__ Bh, const bf16* __restrict__ Bl,
              float* __restrict__ Cf, void* __restrict__ Coh, void* __restrict__ Col,
              const float* __restrict__ bias, const float* __restrict__ resid,
              int K, int ldc,
              long long sA, long long sB, long long sC, long long sR)
{
    extern __shared__ char sm[];
    gemm_tile<EPI, MODE, F16>(Ah, Al, Bh, Bl, Cf, Coh, Col, bias, resid,
                              K, ldc, sA, sB, sC, sR,
                              blockIdx.y * 128, blockIdx.x * 128, blockIdx.z, sm);
}

// ---- combined projection kernel: theta/phi FULL3 (tiles 0..1023) + g SGL ---
__global__ __launch_bounds__(256, 2)
void proj_combo(const bf16* __restrict__ xTh, const bf16* __restrict__ xTl,
                const bf16* __restrict__ wth, const bf16* __restrict__ wtl,
                const bf16* __restrict__ wph, const bf16* __restrict__ wpl,
                bf16* __restrict__ thh, bf16* __restrict__ thl,
                bf16* __restrict__ phh, bf16* __restrict__ phl,
                const float* __restrict__ th_b, const float* __restrict__ ph_b,
                const __half* __restrict__ wg16, const __half* __restrict__ xT16,
                __half* __restrict__ g16, const float* __restrict__ g_bias)
{
    extern __shared__ char sm[];
    const long long sXT = (long long)T_ * C_;
    const long long sTI = (long long)T_ * I_;
    const long long sIT = (long long)I_ * T_;
    const int tile = blockIdx.x;
    if (tile < 1024) {
        const int zsel = tile >> 6;
        const int rem = tile & 63;
        const int bn0 = (rem & 3) * 128;
        const int bm0 = (rem >> 2) * 128;
        const int z = zsel & 7;
        if (zsel < 8)
            gemm_tile<2, 0, false>(xTh, xTl, wth, wtl, nullptr, thh, thl, th_b,
                                   nullptr, C_, I_, sXT, 0, sTI, 0, bm0, bn0, z, sm);
        else
            gemm_tile<2, 0, false>(xTh, xTl, wph, wpl, nullptr, phh, phl, ph_b,
                                   nullptr, C_, I_, sXT, 0, sTI, 0, bm0, bn0, z, sm);
    } else {
        const int t2 = tile - 1024;
        const int bn0 = (t2 & 15) * 128;
        const int bm0 = ((t2 >> 4) & 3) * 128;
        const int z = t2 >> 6;
        gemm_tile<6, 2, true>((const bf16*)wg16, nullptr, (const bf16*)xT16, nullptr,
                              nullptr, g16, nullptr, g_bias, nullptr,
                              C_, T_, 0, sXT, sIT, 0, bm0, bn0, z, sm);
    }
}

// ================= weight prep: one launch, 4 tasks ==========================
__global__ __launch_bounds__(256)
void prep_weights(const float* __restrict__ th_w, const float* __restrict__ ph_w,
                  const float* __restrict__ gw,   const float* __restrict__ Ww,
                  bf16* __restrict__ wth, bf16* __restrict__ wtl,
                  bf16* __restrict__ wph, bf16* __restrict__ wpl,
                  __half* __restrict__ wg16, __half* __restrict__ W16)
{
    const int i = blockIdx.x * 256 + threadIdx.x;
    const int task = blockIdx.y;
    if (i >= I_ * C_) return;
    if (task == 0) {
        float v = th_w[i];
        bf16 h = __float2bfloat16(v);
        wth[i] = h;
        wtl[i] = __float2bfloat16(v - __bfloat162float(h));
    } else if (task == 1) {
        float v = ph_w[i];
        bf16 h = __float2bfloat16(v);
        wph[i] = h;
        wpl[i] = __float2bfloat16(v - __bfloat162float(h));
    } else if (task == 2) {
        wg16[i] = __float2half_rn(gw[i]);
    } else {
        W16[i] = __float2half_rn(Ww[i]);
    }
}

__global__ __launch_bounds__(256)
void transpose_split_x(const float* __restrict__ x, bf16* __restrict__ th,
                       bf16* __restrict__ tl, __half* __restrict__ t16)
{
    __shared__ float tile[32][33];
    const int b = blockIdx.z;
    const int t0 = blockIdx.x * 32, c0 = blockIdx.y * 32;
    const int tx = threadIdx.x, ty = threadIdx.y;  // 32 x 8
    const float* xb = x + (long long)b * C_ * T_;
#pragma unroll
    for (int j = 0; j < 32; j += 8)
        tile[ty + j][tx] = xb[(long long)(c0 + ty + j) * T_ + t0 + tx];
    __syncthreads();
    bf16* thb = th + (long long)b * T_ * C_;
    bf16* tlb = tl + (long long)b * T_ * C_;
    __half* t16b = t16 + (long long)b * T_ * C_;
#pragma unroll
    for (int j = 0; j < 32; j += 8) {
        float v = tile[tx][ty + j];
        long long o = (long long)(t0 + ty + j) * C_ + c0 + tx;
        bf16 h = __float2bfloat16(v);
        thb[o] = h;
        tlb[o] = __float2bfloat16(v - __bfloat162float(h));
        t16b[o] = __float2half_rn(v);
    }
}

// ================= softmax (FFMA-poly exp, rows of f[b*T+t][s]) =============
__device__ __forceinline__ float fast_exp(float x)
{
    float y = x * 1.4426950408889634f;
    float t = y + 12582912.0f;
    int e = __float_as_int(t) - 0x4B400000;
    float r = t - 12582912.0f;
    float f = y - r;
    float pq = 1.5403530393381608e-4f;
    pq = fmaf(pq, f, 1.3333558146428443e-3f);
    pq = fmaf(pq, f, 9.618129107628477e-3f);
    pq = fmaf(pq, f, 5.550410866482158e-2f);
    pq = fmaf(pq, f, 2.402265069591007e-1f);
    pq = fmaf(pq, f, 6.931471805599453e-1f);
    pq = fmaf(pq, f, 1.0f);
    float res = __int_as_float(__float_as_int(pq) + (e << 23));
    return (y > -120.0f) ? res : 0.0f;
}

__global__ __launch_bounds__(256)
void softmax_f16(const float* __restrict__ f, __half* __restrict__ E)
{
    const long long base = (long long)blockIdx.x * T_;
    const int tid = threadIdx.x;
    const int lane = tid & 31, w = tid >> 5;
    __shared__ float red[8];

    float v[8];
    float mx = -1e30f;
#pragma unroll
    for (int i = 0; i < 8; i++) {
        v[i] = f[base + tid + i * 256];
        mx = fmaxf(mx, v[i]);
    }
#pragma unroll
    for (int o = 16; o; o >>= 1) mx = fmaxf(mx, __shfl_xor_sync(~0u, mx, o));
    if (lane == 0) red[w] = mx;
    __syncthreads();
    mx = red[0];
#pragma unroll
    for (int i = 1; i < 8; i++) mx = fmaxf(mx, red[i]);
    __syncthreads();

    float sum = 0.0f;
#pragma unroll
    for (int i = 0; i < 8; i++) {
        v[i] = fast_exp(v[i] - mx);
        sum += v[i];
    }
#pragma unroll
    for (int o = 16; o; o >>= 1) sum += __shfl_xor_sync(~0u, sum, o);
    if (lane == 0) red[w] = sum;
    __syncthreads();
    float tot = 0.0f;
#pragma unroll
    for (int i = 0; i < 8; i++) tot += red[i];
    const float inv = 1.0f / tot;

#pragma unroll
    for (int i = 0; i < 8; i++)
        E[base + tid + i * 256] = __float2half_rn(v[i] * inv);
}

// ================= batchnorm =================
__global__ __launch_bounds__(256)
void bn_stats(const float* __restrict__ s, float* __restrict__ mean, float* __restrict__ rstd)
{
    const int c = blockIdx.x;
    const int tid = threadIdx.x;
    float sum = 0.0f, sq = 0.0f;
    for (int idx = tid; idx < B_ * T_; idx += 256) {
        int b = idx >> 11;
        int t = idx & (T_ - 1);
        float v = s[(long long)b * C_ * T_ + (long long)c * T_ + t];
        sum += v;
        sq = fmaf(v, v, sq);
    }
    __shared__ float r1[256], r2[256];
    r1[tid] = sum; r2[tid] = sq;
    __syncthreads();
#pragma unroll
    for (int st = 128; st > 0; st >>= 1) {
        if (tid < st) { r1[tid] += r1[tid + st]; r2[tid] += r2[tid + st]; }
        __syncthreads();
    }
    if (tid == 0) {
        const float inv_n = 1.0f / (float)(B_ * T_);
        float m = r1[0] * inv_n;
        float var = r2[0] * inv_n - m * m;
        mean[c] = m;
        rstd[c] = rsqrtf(var + BN_EPS);
    }
}

__global__ __launch_bounds__(256)
void bn_apply(float* __restrict__ s, const float* __restrict__ mean,
              const float* __restrict__ rstd, const float* __restrict__ gamma,
              const float* __restrict__ beta)
{
    const int bc = blockIdx.x;
    const int c = bc & (C_ - 1);
    const long long base = (long long)bc * T_;
    const float m = mean[c], r = rstd[c], g = gamma[c], be = beta[c];
    for (int t = threadIdx.x; t < T_; t += 256)
        s[base + t] = fmaf((s[base + t] - m) * r, g, be);
}

// ================= launcher =================
extern "C" void kernel_launch(void* const* d_in, const int* in_sizes, int n_in,
                              void* d_out, int out_size)
{
    const float* x     = (const float*)d_in[0];
    const float* g_w   = (const float*)d_in[1];
    const float* g_b   = (const float*)d_in[2];
    const float* th_w  = (const float*)d_in[3];
    const float* th_b  = (const float*)d_in[4];
    const float* ph_w  = (const float*)d_in[5];
    const float* ph_b  = (const float*)d_in[6];
    const float* W_w   = (const float*)d_in[7];
    const float* W_b   = (const float*)d_in[8];
    const float* gamma = (const float*)d_in[9];
    const float* beta  = (const float*)d_in[10];
    float* out = (float*)d_out;

    bf16 *xTh, *xTl, *wth, *wtl, *wph, *wpl, *thh, *thl, *phh, *phl;
    __half *xT16, *wg16, *W16, *g16, *E, *yT16;
    float *f, *mean, *rstd;
    cudaGetSymbolAddress((void**)&xTh, g_xTh);    cudaGetSymbolAddress((void**)&xTl, g_xTl);
    cudaGetSymbolAddress((void**)&xT16, g_xT16);
    cudaGetSymbolAddress((void**)&wg16, g_wg16);
    cudaGetSymbolAddress((void**)&wth, g_wth);    cudaGetSymbolAddress((void**)&wtl, g_wtl);
    cudaGetSymbolAddress((void**)&wph, g_wph);    cudaGetSymbolAddress((void**)&wpl, g_wpl);
    cudaGetSymbolAddress((void**)&W16, g_W16);
    cudaGetSymbolAddress((void**)&g16, g_g16);
    cudaGetSymbolAddress((void**)&thh, g_thh);    cudaGetSymbolAddress((void**)&thl, g_thl);
    cudaGetSymbolAddress((void**)&phh, g_phh);    cudaGetSymbolAddress((void**)&phl, g_phl);
    cudaGetSymbolAddress((void**)&E, g_E);
    cudaGetSymbolAddress((void**)&yT16, g_yT16);
    cudaGetSymbolAddress((void**)&f, g_f);
    cudaGetSymbolAddress((void**)&mean, g_mean);  cudaGetSymbolAddress((void**)&rstd, g_rstd);

    cudaFuncSetAttribute((const void*)proj_combo,
                         cudaFuncAttributeMaxDynamicSharedMemorySize, SM_FULL3);
    cudaFuncSetAttribute((const void*)mma_gemm<0,0,false>,
                         cudaFuncAttributeMaxDynamicSharedMemorySize, SM_FULL3);
    cudaFuncSetAttribute((const void*)mma_gemm<7,2,true>,
                         cudaFuncAttributeMaxDynamicSharedMemorySize, SM_SGL);
    cudaFuncSetAttribute((const void*)mma_gemm<3,2,true>,
                         cudaFuncAttributeMaxDynamicSharedMemorySize, SM_SGL);

    const long long sX  = (long long)C_ * T_;
    const long long sTI = (long long)T_ * I_;
    const long long sIT = (long long)I_ * T_;
    const long long sF  = (long long)T_ * T_;

    dim3 blk(256);

    // 0) weight prep (one launch) + x transpose/split
    prep_weights<<<dim3((I_ * C_ + 255) / 256, 4), blk>>>(
        th_w, ph_w, g_w, W_w, wth, wtl, wph, wpl, wg16, W16);
    transpose_split_x<<<dim3(T_ / 32, C_ / 32, B_), dim3(32, 8)>>>(x, xTh, xTl, xT16);

    // 1) combined: theta/phi FULL3 (1024 tiles) + g SGL (512 tiles)
    proj_combo<<<1536, blk, SM_FULL3>>>(
        xTh, xTl, wth, wtl, wph, wpl, thh, thl, phh, phl, th_b, ph_b,
        wg16, xT16, g16, g_b);

    // 2) f[t,s] = sum_i thT[t,i]*phT[s,i]  (M=T,N=T,K=I)  FULL3 -> fp32
    mma_gemm<0,0,false><<<dim3(T_ / 128, T_ / 128, B_), blk, SM_FULL3>>>(
        thh, thl, phh, phl, f, nullptr, nullptr, nullptr, nullptr, I_, T_, sTI, sTI, sF, 0);
    // 3) softmax rows -> normalized fp16 E
    softmax_f16<<<B_ * T_, blk>>>(f, E);
    // 4) yT[t,i] = sum_s E[t,s]*g[i,s]  (M=T,N=I,K=T)  SGL f16
    mma_gemm<7,2,true><<<dim3(I_ / 128, T_ / 128, B_), blk, SM_SGL>>>(
        (const bf16*)E, nullptr, (const bf16*)g16, nullptr,
        nullptr, yT16, nullptr, nullptr, nullptr, T_, I_, sF, sIT, sTI, 0);
    // 5) s[c,t] = sum_i W[c,i]*yT[t,i] + Wb[c] + x  (M=C,N=T,K=I)  SGL f16 -> fp32
    mma_gemm<3,2,true><<<dim3(T_ / 128, C_ / 128, B_), blk, SM_SGL>>>(
        (const bf16*)W16, nullptr, (const bf16*)yT16, nullptr,
        out, nullptr, nullptr, W_b, x, I_, T_, 0, sTI, sX, sX);

    // 6) batchnorm
    bn_stats<<<C_, blk>>>(out, mean, rstd);
    bn_apply<<<B_ * C_, blk>>>(out, mean, rstd, gamma, beta);
}

// round 14
// speedup vs baseline: 1.0962x; 1.0962x over previous
#include <cuda_runtime.h>
#include <cuda_bf16.h>
#include <cuda_fp16.h>
#include <math.h>
#include <stdint.h>

#define B_ 8
#define C_ 1024
#define T_ 2048
#define I_ 512
#define BN_EPS 1e-5f

typedef __nv_bfloat16 bf16;

// ================= static scratch =================
__device__ __align__(16) bf16   g_xTh[B_ * T_ * C_];
__device__ __align__(16) bf16   g_xTl[B_ * T_ * C_];
__device__ __align__(16) __half g_xT16[B_ * T_ * C_];
__device__ __align__(16) __half g_wg16[I_ * C_];
__device__ __align__(16) bf16   g_wth[I_ * C_],  g_wtl[I_ * C_];
__device__ __align__(16) bf16   g_wph[I_ * C_],  g_wpl[I_ * C_];
__device__ __align__(16) __half g_W16[C_ * I_];
__device__ __align__(16) __half g_g16[B_ * I_ * T_];
__device__ __align__(16) bf16   g_thh[B_ * T_ * I_], g_thl[B_ * T_ * I_];
__device__ __align__(16) bf16   g_phh[B_ * T_ * I_], g_phl[B_ * T_ * I_];
__device__ __align__(16) float  g_f[33554432];            // [B,T,S] fp32
__device__ __align__(16) __half g_E[33554432];            // fp16 attention
__device__ __align__(16) __half g_yT16[B_ * T_ * I_];
__device__ float g_bnsum[C_], g_bnsq[C_];

// ================= PTX helpers (baseline features only) =================
#define LDSM4(r, a) \
    asm volatile("ldmatrix.sync.aligned.m8n8.x4.shared.b16 {%0,%1,%2,%3}, [%4];" \
        : "=r"((r)[0]), "=r"((r)[1]), "=r"((r)[2]), "=r"((r)[3]) : "r"(a))

#define MMA_BF16(c, a, b) \
    asm volatile("mma.sync.aligned.m16n8k16.row.col.f32.bf16.bf16.f32 " \
        "{%0,%1,%2,%3}, {%4,%5,%6,%7}, {%8,%9}, {%0,%1,%2,%3};" \
        : "+f"((c)[0]), "+f"((c)[1]), "+f"((c)[2]), "+f"((c)[3]) \
        : "r"((a)[0]), "r"((a)[1]), "r"((a)[2]), "r"((a)[3]), \
          "r"((b)[0]), "r"((b)[1]))

#define MMA_F16(c, a, b) \
    asm volatile("mma.sync.aligned.m16n8k16.row.col.f32.f16.f16.f32 " \
        "{%0,%1,%2,%3}, {%4,%5,%6,%7}, {%8,%9}, {%0,%1,%2,%3};" \
        : "+f"((c)[0]), "+f"((c)[1]), "+f"((c)[2]), "+f"((c)[3]) \
        : "r"((a)[0]), "r"((a)[1]), "r"((a)[2]), "r"((a)[3]), \
          "r"((b)[0]), "r"((b)[1]))

#define CP_ASYNC16(saddr, gptr) \
    asm volatile("cp.async.cg.shared.global [%0], [%1], 16;" \
        :: "r"(saddr), "l"(__cvta_generic_to_global(gptr)))
#define CP_COMMIT() asm volatile("cp.async.commit_group;" ::: "memory")

#define REDG_ADD_F32(gptr, v) \
    asm volatile("red.global.add.f32 [%0], %1;" \
        :: "l"(__cvta_generic_to_global(gptr)), "f"(v) : "memory")

// ================= GEMM tile body: 128x128, K-chunk 32 ======================
// D[m,n] = sum_k A[m,k]*B[n,k].  K-major rows, 16-bit elements.
// MODE 0 (FULL3): comps [Ah,Al,Bh,Bl], 3 products, 2-stage
// MODE 2 (SGL)  : comps [A,B],         1 product,  4-stage
// EPI: 0 fp32 | 2 bf16 split+bias[n] | 3 fp32+bias[m]+resid+BN-partials
//      6 f16 single+bias[m] | 7 f16 single
#define ROWB 80
#define COMPB (128 * ROWB)

template <int EPI, int MODE, bool F16>
__device__ __forceinline__ void gemm_tile(
    const bf16* __restrict__ Ah, const bf16* __restrict__ Al,
    const bf16* __restrict__ Bh, const bf16* __restrict__ Bl,
    float* __restrict__ Cf, void* __restrict__ Coh, void* __restrict__ Col,
    const float* __restrict__ bias, const float* __restrict__ resid,
    int K, int ldc, long long sA, long long sB, long long sC, long long sR,
    int bm0, int bn0, int z, char* sm)
{
    constexpr int NCOMP  = (MODE == 0) ? 4 : 2;
    constexpr int BC     = (MODE == 0) ? 2 : 1;
    constexpr int NSTAGE = (MODE == 0) ? 2 : 4;
    constexpr int BUFB = NCOMP * COMPB;
    const uint32_t sbase = (uint32_t)__cvta_generic_to_shared(sm);
    const int tid = threadIdx.x;
    const int lane = tid & 31;
    const int wid = tid >> 5;
    const int wm = (wid >> 1) * 32;
    const int wn = (wid & 1) * 64;

    const bf16* gp[NCOMP];
    gp[0] = Ah + sA * z + (long long)bm0 * K;
    if (MODE == 0) {
        gp[1] = Al + sA * z + (long long)bm0 * K;
        gp[2] = Bh + sB * z + (long long)bn0 * K;
        gp[3] = Bl + sB * z + (long long)bn0 * K;
    } else {
        gp[1] = Bh + sB * z + (long long)bn0 * K;
    }

    float acc[2][8][4];
#pragma unroll
    for (int i = 0; i < 2; i++)
#pragma unroll
        for (int j = 0; j < 8; j++)
#pragma unroll
            for (int q = 0; q < 4; q++) acc[i][j][q] = 0.0f;

    auto load_chunk = [&](int k0, int buf) {
        const uint32_t b = sbase + buf * BUFB;
#pragma unroll
        for (int i = 0; i < NCOMP * 2; i++) {
            const int u = tid + i * 256;
            const int comp = u >> 9;
            const int rem = u & 511;
            const int row = rem >> 2;
            const int un = rem & 3;
            const bf16* g = gp[comp] + (long long)row * K + k0 + un * 8;
            const uint32_t s = b + comp * COMPB + row * ROWB + un * 16;
            CP_ASYNC16(s, g);
        }
        CP_COMMIT();
    };

    auto compute = [&](int buf) {
        const uint32_t b = sbase + buf * BUFB;
        const uint32_t arow = wm + (lane & 15);
        const uint32_t akoff = ((lane >> 4) & 1) * 16;
        const uint32_t brow = wn + ((lane >> 4) << 3) + (lane & 7);
        const uint32_t bkoff = ((lane >> 3) & 1) * 16;
#pragma unroll
        for (int s = 0; s < 2; s++) {
            uint32_t ah[2][4], al[2][4];
#pragma unroll
            for (int mt = 0; mt < 2; mt++) {
                const uint32_t addr = b + (arow + mt * 16) * ROWB + s * 32 + akoff;
                LDSM4(ah[mt], addr);
                if (MODE == 0) LDSM4(al[mt], addr + COMPB);
            }
            const uint32_t bbase = b + BC * COMPB + brow * ROWB + s * 32 + bkoff;
            uint32_t rh[2][4], rl[2][4];
            LDSM4(rh[0], bbase);
            if (MODE == 0) LDSM4(rl[0], bbase + COMPB);
#pragma unroll
            for (int np = 0; np < 4; np++) {
                const int cur = np & 1;
                if (np < 3) {
                    const uint32_t na = bbase + (np + 1) * 16 * ROWB;
                    LDSM4(rh[cur ^ 1], na);
                    if (MODE == 0) LDSM4(rl[cur ^ 1], na + COMPB);
                }
                const int nb = np * 2;
                uint32_t b0[2] = { rh[cur][0], rh[cur][1] };
                uint32_t b1[2] = { rh[cur][2], rh[cur][3] };
                if (F16) {
                    MMA_F16(acc[0][nb],     ah[0], b0);
                    MMA_F16(acc[1][nb],     ah[1], b0);
                    MMA_F16(acc[0][nb + 1], ah[0], b1);
                    MMA_F16(acc[1][nb + 1], ah[1], b1);
                } else {
                    MMA_BF16(acc[0][nb],     ah[0], b0);
                    MMA_BF16(acc[1][nb],     ah[1], b0);
                    MMA_BF16(acc[0][nb + 1], ah[0], b1);
                    MMA_BF16(acc[1][nb + 1], ah[1], b1);
                }
                if (MODE == 0) {
                    uint32_t c0[2] = { rl[cur][0], rl[cur][1] };
                    uint32_t c1[2] = { rl[cur][2], rl[cur][3] };
                    MMA_BF16(acc[0][nb],     ah[0], c0);
                    MMA_BF16(acc[1][nb],     ah[1], c0);
                    MMA_BF16(acc[0][nb + 1], ah[0], c1);
                    MMA_BF16(acc[1][nb + 1], ah[1], c1);
                    MMA_BF16(acc[0][nb],     al[0], b0);
                    MMA_BF16(acc[1][nb],     al[1], b0);
                    MMA_BF16(acc[0][nb + 1], al[0], b1);
                    MMA_BF16(acc[1][nb + 1], al[1], b1);
                }
            }
        }
    };

    const int nch = K / 32;
#pragma unroll
    for (int p = 0; p < NSTAGE - 1; p++)
        load_chunk(p * 32, p);

    for (int c = 0; c < nch; c++) {
        asm volatile("cp.async.wait_group %0;" :: "n"(NSTAGE - 2) : "memory");
        __syncthreads();
        const int nxt = c + NSTAGE - 1;
        if (nxt < nch) load_chunk(nxt * 32, nxt % NSTAGE);
        compute(c % NSTAGE);
    }

    // ---- epilogue ----
    const int r0 = lane >> 2;
    const int cq = (lane & 3) * 2;
#pragma unroll
    for (int mt = 0; mt < 2; mt++) {
        const int mA = bm0 + wm + mt * 16 + r0;
        const int mB = mA + 8;
        float biasA = 0.0f, biasB = 0.0f;
        if (EPI == 3 || EPI == 6) { biasA = bias[mA]; biasB = bias[mB]; }
        const long long rowA = sC * z + (long long)mA * ldc;
        const long long rowB = sC * z + (long long)mB * ldc;
        float sA_ = 0.0f, qA_ = 0.0f, sB_ = 0.0f, qB_ = 0.0f;  // BN partials
#pragma unroll
        for (int nt = 0; nt < 8; nt++) {
            const int n = bn0 + wn + nt * 8 + cq;
            float v0 = acc[mt][nt][0], v1 = acc[mt][nt][1];
            float v2 = acc[mt][nt][2], v3 = acc[mt][nt][3];
            if (EPI == 2) {
                const float bn0v = bias[n], bn1v = bias[n + 1];
                v0 += bn0v; v1 += bn1v; v2 += bn0v; v3 += bn1v;
            }
            if (EPI == 3 || EPI == 6) { v0 += biasA; v1 += biasA; v2 += biasB; v3 += biasB; }
            if (EPI == 0 || EPI == 3) {
                if (EPI == 3) {
                    const long long rA = sR * z + (long long)mA * ldc + n;
                    const long long rB = sR * z + (long long)mB * ldc + n;
                    float2 ra = *(const float2*)(resid + rA);
                    float2 rb = *(const float2*)(resid + rB);
                    v0 += ra.x; v1 += ra.y; v2 += rb.x; v3 += rb.y;
                    sA_ += v0 + v1;
                    qA_ = fmaf(v0, v0, fmaf(v1, v1, qA_));
                    sB_ += v2 + v3;
                    qB_ = fmaf(v2, v2, fmaf(v3, v3, qB_));
                }
                *(float2*)(Cf + rowA + n) = make_float2(v0, v1);
                *(float2*)(Cf + rowB + n) = make_float2(v2, v3);
            } else if (EPI == 6 || EPI == 7) {
                *(__half2*)((__half*)Coh + rowA + n) = __floats2half2_rn(v0, v1);
                *(__half2*)((__half*)Coh + rowB + n) = __floats2half2_rn(v2, v3);
            } else {
                __nv_bfloat162 hA = __floats2bfloat162_rn(v0, v1);
                __nv_bfloat162 hB = __floats2bfloat162_rn(v2, v3);
                __nv_bfloat162 lA = __floats2bfloat162_rn(
                    v0 - __bfloat162float(hA.x), v1 - __bfloat162float(hA.y));
                __nv_bfloat162 lB = __floats2bfloat162_rn(
                    v2 - __bfloat162float(hB.x), v3 - __bfloat162float(hB.y));
                *(__nv_bfloat162*)((bf16*)Coh + rowA + n) = hA;
                *(__nv_bfloat162*)((bf16*)Coh + rowB + n) = hB;
                *(__nv_bfloat162*)((bf16*)Col + rowA + n) = lA;
                *(__nv_bfloat162*)((bf16*)Col + rowB + n) = lB;
            }
        }
        if (EPI == 3) {
            // reduce BN partials across the 4 lanes sharing each row
#pragma unroll
            for (int o = 1; o <= 2; o <<= 1) {
                sA_ += __shfl_xor_sync(~0u, sA_, o);
                qA_ += __shfl_xor_sync(~0u, qA_, o);
                sB_ += __shfl_xor_sync(~0u, sB_, o);
                qB_ += __shfl_xor_sync(~0u, qB_, o);
            }
            if ((lane & 3) == 0) {
                REDG_ADD_F32(&g_bnsum[mA], sA_);
                REDG_ADD_F32(&g_bnsq[mA],  qA_);
                REDG_ADD_F32(&g_bnsum[mB], sB_);
                REDG_ADD_F32(&g_bnsq[mB],  qB_);
            }
        }
    }
}

// smem sizes
#define SM_FULL3 (2 * 4 * COMPB)   // 81920: 2 stages x 4 comps
#define SM_SGL   (4 * 2 * COMPB)   // 81920: 4 stages x 2 comps

// ---- plain wrapper (3D grid, one tile per CTA) ----
template <int EPI, int MODE, bool F16>
__global__ __launch_bounds__(256, 2)
void mma_gemm(const bf16* __restrict__ Ah, const bf16* __restrict__ Al,
              const bf16* __restrict__ Bh, const bf16* __restrict__ Bl,
              float* __restrict__ Cf, void* __restrict__ Coh, void* __restrict__ Col,
              const float* __restrict__ bias, const float* __restrict__ resid,
              int K, int ldc,
              long long sA, long long sB, long long sC, long long sR)
{
    extern __shared__ char sm[];
    gemm_tile<EPI, MODE, F16>(Ah, Al, Bh, Bl, Cf, Coh, Col, bias, resid,
                              K, ldc, sA, sB, sC, sR,
                              blockIdx.y * 128, blockIdx.x * 128, blockIdx.z, sm);
}

// ---- combined projection kernel: theta/phi FULL3 (tiles 0..1023) + g SGL ---
__global__ __launch_bounds__(256, 2)
void proj_combo(const bf16* __restrict__ xTh, const bf16* __restrict__ xTl,
                const bf16* __restrict__ wth, const bf16* __restrict__ wtl,
                const bf16* __restrict__ wph, const bf16* __restrict__ wpl,
                bf16* __restrict__ thh, bf16* __restrict__ thl,
                bf16* __restrict__ phh, bf16* __restrict__ phl,
                const float* __restrict__ th_b, const float* __restrict__ ph_b,
                const __half* __restrict__ wg16, const __half* __restrict__ xT16,
                __half* __restrict__ g16, const float* __restrict__ g_bias)
{
    extern __shared__ char sm[];
    const long long sXT = (long long)T_ * C_;
    const long long sTI = (long long)T_ * I_;
    const long long sIT = (long long)I_ * T_;
    const int tile = blockIdx.x;
    if (tile < 1024) {
        const int zsel = tile >> 6;
        const int rem = tile & 63;
        const int bn0 = (rem & 3) * 128;
        const int bm0 = (rem >> 2) * 128;
        const int z = zsel & 7;
        if (zsel < 8)
            gemm_tile<2, 0, false>(xTh, xTl, wth, wtl, nullptr, thh, thl, th_b,
                                   nullptr, C_, I_, sXT, 0, sTI, 0, bm0, bn0, z, sm);
        else
            gemm_tile<2, 0, false>(xTh, xTl, wph, wpl, nullptr, phh, phl, ph_b,
                                   nullptr, C_, I_, sXT, 0, sTI, 0, bm0, bn0, z, sm);
    } else {
        const int t2 = tile - 1024;
        const int bn0 = (t2 & 15) * 128;
        const int bm0 = ((t2 >> 4) & 3) * 128;
        const int z = t2 >> 6;
        gemm_tile<6, 2, true>((const bf16*)wg16, nullptr, (const bf16*)xT16, nullptr,
                              nullptr, g16, nullptr, g_bias, nullptr,
                              C_, T_, 0, sXT, sIT, 0, bm0, bn0, z, sm);
    }
}

// ================= weight prep: one launch, 4 tasks + BN-acc zeroing ========
__global__ __launch_bounds__(256)
void prep_weights(const float* __restrict__ th_w, const float* __restrict__ ph_w,
                  const float* __restrict__ gw,   const float* __restrict__ Ww,
                  bf16* __restrict__ wth, bf16* __restrict__ wtl,
                  bf16* __restrict__ wph, bf16* __restrict__ wpl,
                  __half* __restrict__ wg16, __half* __restrict__ W16,
                  float* __restrict__ bnsum, float* __restrict__ bnsq)
{
    const int i = blockIdx.x * 256 + threadIdx.x;
    const int task = blockIdx.y;
    if (i >= I_ * C_) return;
    if (task == 0) {
        float v = th_w[i];
        bf16 h = __float2bfloat16(v);
        wth[i] = h;
        wtl[i] = __float2bfloat16(v - __bfloat162float(h));
        if (i < C_) { bnsum[i] = 0.0f; bnsq[i] = 0.0f; }
    } else if (task == 1) {
        float v = ph_w[i];
        bf16 h = __float2bfloat16(v);
        wph[i] = h;
        wpl[i] = __float2bfloat16(v - __bfloat162float(h));
    } else if (task == 2) {
        wg16[i] = __float2half_rn(gw[i]);
    } else {
        W16[i] = __float2half_rn(Ww[i]);
    }
}

__global__ __launch_bounds__(256)
void transpose_split_x(const float* __restrict__ x, bf16* __restrict__ th,
                       bf16* __restrict__ tl, __half* __restrict__ t16)
{
    __shared__ float tile[32][33];
    const int b = blockIdx.z;
    const int t0 = blockIdx.x * 32, c0 = blockIdx.y * 32;
    const int tx = threadIdx.x, ty = threadIdx.y;  // 32 x 8
    const float* xb = x + (long long)b * C_ * T_;
#pragma unroll
    for (int j = 0; j < 32; j += 8)
        tile[ty + j][tx] = xb[(long long)(c0 + ty + j) * T_ + t0 + tx];
    __syncthreads();
    bf16* thb = th + (long long)b * T_ * C_;
    bf16* tlb = tl + (long long)b * T_ * C_;
    __half* t16b = t16 + (long long)b * T_ * C_;
#pragma unroll
    for (int j = 0; j < 32; j += 8) {
        float v = tile[tx][ty + j];
        long long o = (long long)(t0 + ty + j) * C_ + c0 + tx;
        bf16 h = __float2bfloat16(v);
        thb[o] = h;
        tlb[o] = __float2bfloat16(v - __bfloat162float(h));
        t16b[o] = __float2half_rn(v);
    }
}

// ================= softmax (FFMA-poly exp, rows of f[b*T+t][s]) =============
__device__ __forceinline__ float fast_exp(float x)
{
    float y = x * 1.4426950408889634f;
    float t = y + 12582912.0f;
    int e = __float_as_int(t) - 0x4B400000;
    float r = t - 12582912.0f;
    float f = y - r;
    float pq = 1.5403530393381608e-4f;
    pq = fmaf(pq, f, 1.3333558146428443e-3f);
    pq = fmaf(pq, f, 9.618129107628477e-3f);
    pq = fmaf(pq, f, 5.550410866482158e-2f);
    pq = fmaf(pq, f, 2.402265069591007e-1f);
    pq = fmaf(pq, f, 6.931471805599453e-1f);
    pq = fmaf(pq, f, 1.0f);
    float res = __int_as_float(__float_as_int(pq) + (e << 23));
    return (y > -120.0f) ? res : 0.0f;
}

__global__ __launch_bounds__(256)
void softmax_f16(const float* __restrict__ f, __half* __restrict__ E)
{
    const long long base = (long long)blockIdx.x * T_;
    const int tid = threadIdx.x;
    const int lane = tid & 31, w = tid >> 5;
    __shared__ float red[8];

    float v[8];
    float mx = -1e30f;
#pragma unroll
    for (int i = 0; i < 8; i++) {
        v[i] = f[base + tid + i * 256];
        mx = fmaxf(mx, v[i]);
    }
#pragma unroll
    for (int o = 16; o; o >>= 1) mx = fmaxf(mx, __shfl_xor_sync(~0u, mx, o));
    if (lane == 0) red[w] = mx;
    __syncthreads();
    mx = red[0];
#pragma unroll
    for (int i = 1; i < 8; i++) mx = fmaxf(mx, red[i]);
    __syncthreads();

    float sum = 0.0f;
#pragma unroll
    for (int i = 0; i < 8; i++) {
        v[i] = fast_exp(v[i] - mx);
        sum += v[i];
    }
#pragma unroll
    for (int o = 16; o; o >>= 1) sum += __shfl_xor_sync(~0u, sum, o);
    if (lane == 0) red[w] = sum;
    __syncthreads();
    float tot = 0.0f;
#pragma unroll
    for (int i = 0; i < 8; i++) tot += red[i];
    const float inv = 1.0f / tot;

#pragma unroll
    for (int i = 0; i < 8; i++)
        E[base + tid + i * 256] = __float2half_rn(v[i] * inv);
}

// ================= batchnorm apply (stats from fused accumulators) ==========
__global__ __launch_bounds__(256)
void bn_apply(float* __restrict__ s, const float* __restrict__ bnsum,
              const float* __restrict__ bnsq, const float* __restrict__ gamma,
              const float* __restrict__ beta)
{
    const int bc = blockIdx.x;
    const int c = bc & (C_ - 1);
    const long long base = (long long)bc * T_;
    const float inv_n = 1.0f / (float)(B_ * T_);
    const float m = bnsum[c] * inv_n;
    const float var = bnsq[c] * inv_n - m * m;
    const float r = rsqrtf(var + BN_EPS);
    const float g = gamma[c], be = beta[c];
    for (int t = threadIdx.x; t < T_; t += 256)
        s[base + t] = fmaf((s[base + t] - m) * r, g, be);
}

// ================= launcher =================
extern "C" void kernel_launch(void* const* d_in, const int* in_sizes, int n_in,
                              void* d_out, int out_size)
{
    const float* x     = (const float*)d_in[0];
    const float* g_w   = (const float*)d_in[1];
    const float* g_b   = (const float*)d_in[2];
    const float* th_w  = (const float*)d_in[3];
    const float* th_b  = (const float*)d_in[4];
    const float* ph_w  = (const float*)d_in[5];
    const float* ph_b  = (const float*)d_in[6];
    const float* W_w   = (const float*)d_in[7];
    const float* W_b   = (const float*)d_in[8];
    const float* gamma = (const float*)d_in[9];
    const float* beta  = (const float*)d_in[10];
    float* out = (float*)d_out;

    bf16 *xTh, *xTl, *wth, *wtl, *wph, *wpl, *thh, *thl, *phh, *phl;
    __half *xT16, *wg16, *W16, *g16, *E, *yT16;
    float *f, *bnsum, *bnsq;
    cudaGetSymbolAddress((void**)&xTh, g_xTh);    cudaGetSymbolAddress((void**)&xTl, g_xTl);
    cudaGetSymbolAddress((void**)&xT16, g_xT16);
    cudaGetSymbolAddress((void**)&wg16, g_wg16);
    cudaGetSymbolAddress((void**)&wth, g_wth);    cudaGetSymbolAddress((void**)&wtl, g_wtl);
    cudaGetSymbolAddress((void**)&wph, g_wph);    cudaGetSymbolAddress((void**)&wpl, g_wpl);
    cudaGetSymbolAddress((void**)&W16, g_W16);
    cudaGetSymbolAddress((void**)&g16, g_g16);
    cudaGetSymbolAddress((void**)&thh, g_thh);    cudaGetSymbolAddress((void**)&thl, g_thl);
    cudaGetSymbolAddress((void**)&phh, g_phh);    cudaGetSymbolAddress((void**)&phl, g_phl);
    cudaGetSymbolAddress((void**)&E, g_E);
    cudaGetSymbolAddress((void**)&yT16, g_yT16);
    cudaGetSymbolAddress((void**)&f, g_f);
    cudaGetSymbolAddress((void**)&bnsum, g_bnsum); cudaGetSymbolAddress((void**)&bnsq, g_bnsq);

    cudaFuncSetAttribute((const void*)proj_combo,
                         cudaFuncAttributeMaxDynamicSharedMemorySize, SM_FULL3);
    cudaFuncSetAttribute((const void*)mma_gemm<0,0,false>,
                         cudaFuncAttributeMaxDynamicSharedMemorySize, SM_FULL3);
    cudaFuncSetAttribute((const void*)mma_gemm<7,2,true>,
                         cudaFuncAttributeMaxDynamicSharedMemorySize, SM_SGL);
    cudaFuncSetAttribute((const void*)mma_gemm<3,2,true>,
                         cudaFuncAttributeMaxDynamicSharedMemorySize, SM_SGL);

    const long long sX  = (long long)C_ * T_;
    const long long sTI = (long long)T_ * I_;
    const long long sIT = (long long)I_ * T_;
    const long long sF  = (long long)T_ * T_;

    dim3 blk(256);

    // 0) weight prep (+BN accumulator zero) + x transpose/split
    prep_weights<<<dim3((I_ * C_ + 255) / 256, 4), blk>>>(
        th_w, ph_w, g_w, W_w, wth, wtl, wph, wpl, wg16, W16, bnsum, bnsq);
    transpose_split_x<<<dim3(T_ / 32, C_ / 32, B_), dim3(32, 8)>>>(x, xTh, xTl, xT16);

    // 1) combined: theta/phi FULL3 (1024 tiles) + g SGL (512 tiles)
    proj_combo<<<1536, blk, SM_FULL3>>>(
        xTh, xTl, wth, wtl, wph, wpl, thh, thl, phh, phl, th_b, ph_b,
        wg16, xT16, g16, g_b);

    // 2) f[t,s] = sum_i thT[t,i]*phT[s,i]  (M=T,N=T,K=I)  FULL3 -> fp32
    mma_gemm<0,0,false><<<dim3(T_ / 128, T_ / 128, B_), blk, SM_FULL3>>>(
        thh, thl, phh, phl, f, nullptr, nullptr, nullptr, nullptr, I_, T_, sTI, sTI, sF, 0);
    // 3) softmax rows -> normalized fp16 E
    softmax_f16<<<B_ * T_, blk>>>(f, E);
    // 4) yT[t,i] = sum_s E[t,s]*g[i,s]  (M=T,N=I,K=T)  SGL f16
    mma_gemm<7,2,true><<<dim3(I_ / 128, T_ / 128, B_), blk, SM_SGL>>>(
        (const bf16*)E, nullptr, (const bf16*)g16, nullptr,
        nullptr, yT16, nullptr, nullptr, nullptr, T_, I_, sF, sIT, sTI, 0);
    // 5) s[c,t] = sum_i W[c,i]*yT[t,i] + Wb[c] + x, fused BN partial sums
    mma_gemm<3,2,true><<<dim3(T_ / 128, C_ / 128, B_), blk, SM_SGL>>>(
        (const bf16*)W16, nullptr, (const bf16*)yT16, nullptr,
        out, nullptr, nullptr, W_b, x, I_, T_, 0, sTI, sX, sX);

    // 6) batchnorm apply (stats already accumulated)
    bn_apply<<<B_ * C_, blk>>>(out, bnsum, bnsq, gamma, beta);
}

// round 15
// speedup vs baseline: 1.1172x; 1.0192x over previous
#include <cuda_runtime.h>
#include <cuda_bf16.h>
#include <cuda_fp16.h>
#include <math.h>
#include <stdint.h>

#define B_ 8
#define C_ 1024
#define T_ 2048
#define I_ 512
#define BN_EPS 1e-5f

typedef __nv_bfloat16 bf16;

// ================= static scratch =================
__device__ __align__(16) bf16   g_xTh[B_ * T_ * C_];
__device__ __align__(16) bf16   g_xTl[B_ * T_ * C_];
__device__ __align__(16) __half g_xT16[B_ * T_ * C_];
__device__ __align__(16) __half g_wg16[I_ * C_];
__device__ __align__(16) bf16   g_wth[I_ * C_],  g_wtl[I_ * C_];
__device__ __align__(16) bf16   g_wph[I_ * C_],  g_wpl[I_ * C_];
__device__ __align__(16) __half g_W16[C_ * I_];
__device__ __align__(16) __half g_g16[B_ * I_ * T_];
__device__ __align__(16) bf16   g_thh[B_ * T_ * I_], g_thl[B_ * T_ * I_];
__device__ __align__(16) bf16   g_phh[B_ * T_ * I_], g_phl[B_ * T_ * I_];
__device__ __align__(16) float  g_f[33554432];            // [B,T,S] fp32
__device__ __align__(16) __half g_E[33554432];            // fp16 attention
__device__ __align__(16) __half g_yT16[B_ * T_ * I_];
__device__ float g_bnsum[C_], g_bnsq[C_];

// ================= PTX helpers (baseline features only) =================
#define LDSM4(r, a) \
    asm volatile("ldmatrix.sync.aligned.m8n8.x4.shared.b16 {%0,%1,%2,%3}, [%4];" \
        : "=r"((r)[0]), "=r"((r)[1]), "=r"((r)[2]), "=r"((r)[3]) : "r"(a))

#define MMA_BF16(c, a, b) \
    asm volatile("mma.sync.aligned.m16n8k16.row.col.f32.bf16.bf16.f32 " \
        "{%0,%1,%2,%3}, {%4,%5,%6,%7}, {%8,%9}, {%0,%1,%2,%3};" \
        : "+f"((c)[0]), "+f"((c)[1]), "+f"((c)[2]), "+f"((c)[3]) \
        : "r"((a)[0]), "r"((a)[1]), "r"((a)[2]), "r"((a)[3]), \
          "r"((b)[0]), "r"((b)[1]))

#define MMA_F16(c, a, b) \
    asm volatile("mma.sync.aligned.m16n8k16.row.col.f32.f16.f16.f32 " \
        "{%0,%1,%2,%3}, {%4,%5,%6,%7}, {%8,%9}, {%0,%1,%2,%3};" \
        : "+f"((c)[0]), "+f"((c)[1]), "+f"((c)[2]), "+f"((c)[3]) \
        : "r"((a)[0]), "r"((a)[1]), "r"((a)[2]), "r"((a)[3]), \
          "r"((b)[0]), "r"((b)[1]))

#define CP_ASYNC16(saddr, gptr) \
    asm volatile("cp.async.cg.shared.global [%0], [%1], 16;" \
        :: "r"(saddr), "l"(__cvta_generic_to_global(gptr)))
#define CP_COMMIT() asm volatile("cp.async.commit_group;" ::: "memory")

#define REDG_ADD_F32(gptr, v) \
    asm volatile("red.global.add.f32 [%0], %1;" \
        :: "l"(__cvta_generic_to_global(gptr)), "f"(v) : "memory")

// ================= GEMM tile body: 128x128, K-chunk 32 ======================
// MODE 0 (FULL3): comps [Ah,Al,Bh,Bl], 3 products, 2-stage
// MODE 2 (SGL)  : comps [A,B],         1 product,  4-stage
// EPI: 0 fp32 | 2 bf16 split+bias[n] | 3 fp32+bias[m]+resid+BN-partials
//      6 f16 single+bias[m] | 7 f16 single
#define ROWB 80
#define COMPB (128 * ROWB)

template <int EPI, int MODE, bool F16>
__device__ __forceinline__ void gemm_tile(
    const bf16* __restrict__ Ah, const bf16* __restrict__ Al,
    const bf16* __restrict__ Bh, const bf16* __restrict__ Bl,
    float* __restrict__ Cf, void* __restrict__ Coh, void* __restrict__ Col,
    const float* __restrict__ bias, const float* __restrict__ resid,
    int K, int ldc, long long sA, long long sB, long long sC, long long sR,
    int bm0, int bn0, int z, char* sm)
{
    constexpr int NCOMP  = (MODE == 0) ? 4 : 2;
    constexpr int BC     = (MODE == 0) ? 2 : 1;
    constexpr int NSTAGE = (MODE == 0) ? 2 : 4;
    constexpr int BUFB = NCOMP * COMPB;
    const uint32_t sbase = (uint32_t)__cvta_generic_to_shared(sm);
    const int tid = threadIdx.x;
    const int lane = tid & 31;
    const int wid = tid >> 5;
    const int wm = (wid >> 1) * 32;
    const int wn = (wid & 1) * 64;

    const bf16* gp[NCOMP];
    gp[0] = Ah + sA * z + (long long)bm0 * K;
    if (MODE == 0) {
        gp[1] = Al + sA * z + (long long)bm0 * K;
        gp[2] = Bh + sB * z + (long long)bn0 * K;
        gp[3] = Bl + sB * z + (long long)bn0 * K;
    } else {
        gp[1] = Bh + sB * z + (long long)bn0 * K;
    }

    float acc[2][8][4];
#pragma unroll
    for (int i = 0; i < 2; i++)
#pragma unroll
        for (int j = 0; j < 8; j++)
#pragma unroll
            for (int q = 0; q < 4; q++) acc[i][j][q] = 0.0f;

    auto load_chunk = [&](int k0, int buf) {
        const uint32_t b = sbase + buf * BUFB;
#pragma unroll
        for (int i = 0; i < NCOMP * 2; i++) {
            const int u = tid + i * 256;
            const int comp = u >> 9;
            const int rem = u & 511;
            const int row = rem >> 2;
            const int un = rem & 3;
            const bf16* g = gp[comp] + (long long)row * K + k0 + un * 8;
            const uint32_t s = b + comp * COMPB + row * ROWB + un * 16;
            CP_ASYNC16(s, g);
        }
        CP_COMMIT();
    };

    auto compute = [&](int buf) {
        const uint32_t b = sbase + buf * BUFB;
        const uint32_t arow = wm + (lane & 15);
        const uint32_t akoff = ((lane >> 4) & 1) * 16;
        const uint32_t brow = wn + ((lane >> 4) << 3) + (lane & 7);
        const uint32_t bkoff = ((lane >> 3) & 1) * 16;
#pragma unroll
        for (int s = 0; s < 2; s++) {
            uint32_t ah[2][4], al[2][4];
#pragma unroll
            for (int mt = 0; mt < 2; mt++) {
                const uint32_t addr = b + (arow + mt * 16) * ROWB + s * 32 + akoff;
                LDSM4(ah[mt], addr);
                if (MODE == 0) LDSM4(al[mt], addr + COMPB);
            }
            const uint32_t bbase = b + BC * COMPB + brow * ROWB + s * 32 + bkoff;
            uint32_t rh[2][4], rl[2][4];
            LDSM4(rh[0], bbase);
            if (MODE == 0) LDSM4(rl[0], bbase + COMPB);
#pragma unroll
            for (int np = 0; np < 4; np++) {
                const int cur = np & 1;
                if (np < 3) {
                    const uint32_t na = bbase + (np + 1) * 16 * ROWB;
                    LDSM4(rh[cur ^ 1], na);
                    if (MODE == 0) LDSM4(rl[cur ^ 1], na + COMPB);
                }
                const int nb = np * 2;
                uint32_t b0[2] = { rh[cur][0], rh[cur][1] };
                uint32_t b1[2] = { rh[cur][2], rh[cur][3] };
                if (F16) {
                    MMA_F16(acc[0][nb],     ah[0], b0);
                    MMA_F16(acc[1][nb],     ah[1], b0);
                    MMA_F16(acc[0][nb + 1], ah[0], b1);
                    MMA_F16(acc[1][nb + 1], ah[1], b1);
                } else {
                    MMA_BF16(acc[0][nb],     ah[0], b0);
                    MMA_BF16(acc[1][nb],     ah[1], b0);
                    MMA_BF16(acc[0][nb + 1], ah[0], b1);
                    MMA_BF16(acc[1][nb + 1], ah[1], b1);
                }
                if (MODE == 0) {
                    uint32_t c0[2] = { rl[cur][0], rl[cur][1] };
                    uint32_t c1[2] = { rl[cur][2], rl[cur][3] };
                    MMA_BF16(acc[0][nb],     ah[0], c0);
                    MMA_BF16(acc[1][nb],     ah[1], c0);
                    MMA_BF16(acc[0][nb + 1], ah[0], c1);
                    MMA_BF16(acc[1][nb + 1], ah[1], c1);
                    MMA_BF16(acc[0][nb],     al[0], b0);
                    MMA_BF16(acc[1][nb],     al[1], b0);
                    MMA_BF16(acc[0][nb + 1], al[0], b1);
                    MMA_BF16(acc[1][nb + 1], al[1], b1);
                }
            }
        }
    };

    const int nch = K / 32;
#pragma unroll
    for (int p = 0; p < NSTAGE - 1; p++)
        load_chunk(p * 32, p);

    for (int c = 0; c < nch; c++) {
        asm volatile("cp.async.wait_group %0;" :: "n"(NSTAGE - 2) : "memory");
        __syncthreads();
        const int nxt = c + NSTAGE - 1;
        if (nxt < nch) load_chunk(nxt * 32, nxt % NSTAGE);
        compute(c % NSTAGE);
    }

    // ---- epilogue ----
    const int r0 = lane >> 2;
    const int cq = (lane & 3) * 2;
#pragma unroll
    for (int mt = 0; mt < 2; mt++) {
        const int mA = bm0 + wm + mt * 16 + r0;
        const int mB = mA + 8;
        float biasA = 0.0f, biasB = 0.0f;
        if (EPI == 3 || EPI == 6) { biasA = bias[mA]; biasB = bias[mB]; }
        const long long rowA = sC * z + (long long)mA * ldc;
        const long long rowB = sC * z + (long long)mB * ldc;
        float sA_ = 0.0f, qA_ = 0.0f, sB_ = 0.0f, qB_ = 0.0f;
#pragma unroll
        for (int nt = 0; nt < 8; nt++) {
            const int n = bn0 + wn + nt * 8 + cq;
            float v0 = acc[mt][nt][0], v1 = acc[mt][nt][1];
            float v2 = acc[mt][nt][2], v3 = acc[mt][nt][3];
            if (EPI == 2) {
                const float bn0v = bias[n], bn1v = bias[n + 1];
                v0 += bn0v; v1 += bn1v; v2 += bn0v; v3 += bn1v;
            }
            if (EPI == 3 || EPI == 6) { v0 += biasA; v1 += biasA; v2 += biasB; v3 += biasB; }
            if (EPI == 0 || EPI == 3) {
                if (EPI == 3) {
                    const long long rA = sR * z + (long long)mA * ldc + n;
                    const long long rB = sR * z + (long long)mB * ldc + n;
                    float2 ra = *(const float2*)(resid + rA);
                    float2 rb = *(const float2*)(resid + rB);
                    v0 += ra.x; v1 += ra.y; v2 += rb.x; v3 += rb.y;
                    sA_ += v0 + v1;
                    qA_ = fmaf(v0, v0, fmaf(v1, v1, qA_));
                    sB_ += v2 + v3;
                    qB_ = fmaf(v2, v2, fmaf(v3, v3, qB_));
                }
                *(float2*)(Cf + rowA + n) = make_float2(v0, v1);
                *(float2*)(Cf + rowB + n) = make_float2(v2, v3);
            } else if (EPI == 6 || EPI == 7) {
                *(__half2*)((__half*)Coh + rowA + n) = __floats2half2_rn(v0, v1);
                *(__half2*)((__half*)Coh + rowB + n) = __floats2half2_rn(v2, v3);
            } else {
                __nv_bfloat162 hA = __floats2bfloat162_rn(v0, v1);
                __nv_bfloat162 hB = __floats2bfloat162_rn(v2, v3);
                __nv_bfloat162 lA = __floats2bfloat162_rn(
                    v0 - __bfloat162float(hA.x), v1 - __bfloat162float(hA.y));
                __nv_bfloat162 lB = __floats2bfloat162_rn(
                    v2 - __bfloat162float(hB.x), v3 - __bfloat162float(hB.y));
                *(__nv_bfloat162*)((bf16*)Coh + rowA + n) = hA;
                *(__nv_bfloat162*)((bf16*)Coh + rowB + n) = hB;
                *(__nv_bfloat162*)((bf16*)Col + rowA + n) = lA;
                *(__nv_bfloat162*)((bf16*)Col + rowB + n) = lB;
            }
        }
        if (EPI == 3) {
#pragma unroll
            for (int o = 1; o <= 2; o <<= 1) {
                sA_ += __shfl_xor_sync(~0u, sA_, o);
                qA_ += __shfl_xor_sync(~0u, qA_, o);
                sB_ += __shfl_xor_sync(~0u, sB_, o);
                qB_ += __shfl_xor_sync(~0u, qB_, o);
            }
            if ((lane & 3) == 0) {
                REDG_ADD_F32(&g_bnsum[mA], sA_);
                REDG_ADD_F32(&g_bnsq[mA],  qA_);
                REDG_ADD_F32(&g_bnsum[mB], sB_);
                REDG_ADD_F32(&g_bnsq[mB],  qB_);
            }
        }
    }
}

#define SM_FULL3 (2 * 4 * COMPB)   // 81920
#define SM_SGL   (4 * 2 * COMPB)   // 81920

// ---- plain wrapper ----
template <int EPI, int MODE, bool F16>
__global__ __launch_bounds__(256, 2)
void mma_gemm(const bf16* __restrict__ Ah, const bf16* __restrict__ Al,
              const bf16* __restrict__ Bh, const bf16* __restrict__ Bl,
              float* __restrict__ Cf, void* __restrict__ Coh, void* __restrict__ Col,
              const float* __restrict__ bias, const float* __restrict__ resid,
              int K, int ldc,
              long long sA, long long sB, long long sC, long long sR)
{
    extern __shared__ char sm[];
    gemm_tile<EPI, MODE, F16>(Ah, Al, Bh, Bl, Cf, Coh, Col, bias, resid,
                              K, ldc, sA, sB, sC, sR,
                              blockIdx.y * 128, blockIdx.x * 128, blockIdx.z, sm);
}

// ---- combined projection kernel ----
__global__ __launch_bounds__(256, 2)
void proj_combo(const bf16* __restrict__ xTh, const bf16* __restrict__ xTl,
                const bf16* __restrict__ wth, const bf16* __restrict__ wtl,
                const bf16* __restrict__ wph, const bf16* __restrict__ wpl,
                bf16* __restrict__ thh, bf16* __restrict__ thl,
                bf16* __restrict__ phh, bf16* __restrict__ phl,
                const float* __restrict__ th_b, const float* __restrict__ ph_b,
                const __half* __restrict__ wg16, const __half* __restrict__ xT16,
                __half* __restrict__ g16, const float* __restrict__ g_bias)
{
    extern __shared__ char sm[];
    const long long sXT = (long long)T_ * C_;
    const long long sTI = (long long)T_ * I_;
    const long long sIT = (long long)I_ * T_;
    const int tile = blockIdx.x;
    if (tile < 1024) {
        const int zsel = tile >> 6;
        const int rem = tile & 63;
        const int bn0 = (rem & 3) * 128;
        const int bm0 = (rem >> 2) * 128;
        const int z = zsel & 7;
        if (zsel < 8)
            gemm_tile<2, 0, false>(xTh, xTl, wth, wtl, nullptr, thh, thl, th_b,
                                   nullptr, C_, I_, sXT, 0, sTI, 0, bm0, bn0, z, sm);
        else
            gemm_tile<2, 0, false>(xTh, xTl, wph, wpl, nullptr, phh, phl, ph_b,
                                   nullptr, C_, I_, sXT, 0, sTI, 0, bm0, bn0, z, sm);
    } else {
        const int t2 = tile - 1024;
        const int bn0 = (t2 & 15) * 128;
        const int bm0 = ((t2 >> 4) & 3) * 128;
        const int z = t2 >> 6;
        gemm_tile<6, 2, true>((const bf16*)wg16, nullptr, (const bf16*)xT16, nullptr,
                              nullptr, g16, nullptr, g_bias, nullptr,
                              C_, T_, 0, sXT, sIT, 0, bm0, bn0, z, sm);
    }
}

// ================= prep combo: x transpose/split (blocks 0..16383) +
//                   weight prep (blocks 16384..24575) + BN zero ==============
__global__ __launch_bounds__(256)
void prep_combo(const float* __restrict__ x,
                bf16* __restrict__ xth, bf16* __restrict__ xtl, __half* __restrict__ xt16,
                const float* __restrict__ th_w, const float* __restrict__ ph_w,
                const float* __restrict__ gw,   const float* __restrict__ Ww,
                bf16* __restrict__ wth, bf16* __restrict__ wtl,
                bf16* __restrict__ wph, bf16* __restrict__ wpl,
                __half* __restrict__ wg16, __half* __restrict__ W16,
                float* __restrict__ bnsum, float* __restrict__ bnsq)
{
    const int blk = blockIdx.x;
    const int tid = threadIdx.x;
    if (blk < 16384) {
        // transpose tile: bx 0..63 (t), by 0..31 (c), bz 0..7 (b)
        __shared__ float tile[32][33];
        const int bx = blk & 63, by = (blk >> 6) & 31, b = blk >> 11;
        const int t0 = bx * 32, c0 = by * 32;
        const int tx = tid & 31, ty = tid >> 5;  // 32 x 8
        const float* xb = x + (long long)b * C_ * T_;
#pragma unroll
        for (int j = 0; j < 32; j += 8)
            tile[ty + j][tx] = xb[(long long)(c0 + ty + j) * T_ + t0 + tx];
        __syncthreads();
        bf16* thb = xth + (long long)b * T_ * C_;
        bf16* tlb = xtl + (long long)b * T_ * C_;
        __half* t16b = xt16 + (long long)b * T_ * C_;
#pragma unroll
        for (int j = 0; j < 32; j += 8) {
            float v = tile[tx][ty + j];
            long long o = (long long)(t0 + ty + j) * C_ + c0 + tx;
            bf16 h = __float2bfloat16(v);
            thb[o] = h;
            tlb[o] = __float2bfloat16(v - __bfloat162float(h));
            t16b[o] = __float2half_rn(v);
        }
    } else {
        const int b2 = blk - 16384;
        const int task = b2 >> 11;
        const int i = (b2 & 2047) * 256 + tid;
        if (i >= I_ * C_) return;
        if (task == 0) {
            float v = th_w[i];
            bf16 h = __float2bfloat16(v);
            wth[i] = h;
            wtl[i] = __float2bfloat16(v - __bfloat162float(h));
            if (i < C_) { bnsum[i] = 0.0f; bnsq[i] = 0.0f; }
        } else if (task == 1) {
            float v = ph_w[i];
            bf16 h = __float2bfloat16(v);
            wph[i] = h;
            wpl[i] = __float2bfloat16(v - __bfloat162float(h));
        } else if (task == 2) {
            wg16[i] = __float2half_rn(gw[i]);
        } else {
            W16[i] = __float2half_rn(Ww[i]);
        }
    }
}

// ================= softmax (vectorized, rows of f[b*T+t][s]) ================
__device__ __forceinline__ float fast_exp(float x)
{
    float y = x * 1.4426950408889634f;
    float t = y + 12582912.0f;
    int e = __float_as_int(t) - 0x4B400000;
    float r = t - 12582912.0f;
    float f = y - r;
    float pq = 1.5403530393381608e-4f;
    pq = fmaf(pq, f, 1.3333558146428443e-3f);
    pq = fmaf(pq, f, 9.618129107628477e-3f);
    pq = fmaf(pq, f, 5.550410866482158e-2f);
    pq = fmaf(pq, f, 2.402265069591007e-1f);
    pq = fmaf(pq, f, 6.931471805599453e-1f);
    pq = fmaf(pq, f, 1.0f);
    float res = __int_as_float(__float_as_int(pq) + (e << 23));
    return (y > -120.0f) ? res : 0.0f;
}

__global__ __launch_bounds__(256)
void softmax_f16(const float* __restrict__ f, __half* __restrict__ E)
{
    const long long base = (long long)blockIdx.x * T_;
    const int tid = threadIdx.x;
    const int lane = tid & 31, w = tid >> 5;
    __shared__ float red[8];

    // 8 contiguous elements per thread
    float4 a = *(const float4*)(f + base + tid * 8);
    float4 bq = *(const float4*)(f + base + tid * 8 + 4);
    float v[8] = { a.x, a.y, a.z, a.w, bq.x, bq.y, bq.z, bq.w };

    float mx = v[0];
#pragma unroll
    for (int i = 1; i < 8; i++) mx = fmaxf(mx, v[i]);
#pragma unroll
    for (int o = 16; o; o >>= 1) mx = fmaxf(mx, __shfl_xor_sync(~0u, mx, o));
    if (lane == 0) red[w] = mx;
    __syncthreads();
    mx = red[0];
#pragma unroll
    for (int i = 1; i < 8; i++) mx = fmaxf(mx, red[i]);
    __syncthreads();

    float sum = 0.0f;
#pragma unroll
    for (int i = 0; i < 8; i++) {
        v[i] = fast_exp(v[i] - mx);
        sum += v[i];
    }
#pragma unroll
    for (int o = 16; o; o >>= 1) sum += __shfl_xor_sync(~0u, sum, o);
    if (lane == 0) red[w] = sum;
    __syncthreads();
    float tot = 0.0f;
#pragma unroll
    for (int i = 0; i < 8; i++) tot += red[i];
    const float inv = 1.0f / tot;

    __half2 h0 = __floats2half2_rn(v[0] * inv, v[1] * inv);
    __half2 h1 = __floats2half2_rn(v[2] * inv, v[3] * inv);
    __half2 h2 = __floats2half2_rn(v[4] * inv, v[5] * inv);
    __half2 h3 = __floats2half2_rn(v[6] * inv, v[7] * inv);
    uint4 pack;
    pack.x = *reinterpret_cast<uint32_t*>(&h0);
    pack.y = *reinterpret_cast<uint32_t*>(&h1);
    pack.z = *reinterpret_cast<uint32_t*>(&h2);
    pack.w = *reinterpret_cast<uint32_t*>(&h3);
    *(uint4*)(E + base + tid * 8) = pack;
}

// ================= batchnorm apply (float4, stats from accumulators) ========
__global__ __launch_bounds__(256)
void bn_apply(float* __restrict__ s, const float* __restrict__ bnsum,
              const float* __restrict__ bnsq, const float* __restrict__ gamma,
              const float* __restrict__ beta)
{
    const int bc = blockIdx.x;
    const int c = bc & (C_ - 1);
    const long long base = (long long)bc * T_;
    const float inv_n = 1.0f / (float)(B_ * T_);
    const float m = bnsum[c] * inv_n;
    const float var = bnsq[c] * inv_n - m * m;
    const float r = rsqrtf(var + BN_EPS);
    const float g = gamma[c], be = beta[c];
    const int tid = threadIdx.x;
#pragma unroll
    for (int i = 0; i < 2; i++) {
        float4* p = (float4*)(s + base + (tid + i * 256) * 4);
        float4 v = *p;
        v.x = fmaf((v.x - m) * r, g, be);
        v.y = fmaf((v.y - m) * r, g, be);
        v.z = fmaf((v.z - m) * r, g, be);
        v.w = fmaf((v.w - m) * r, g, be);
        *p = v;
    }
}

// ================= launcher =================
extern "C" void kernel_launch(void* const* d_in, const int* in_sizes, int n_in,
                              void* d_out, int out_size)
{
    const float* x     = (const float*)d_in[0];
    const float* g_w   = (const float*)d_in[1];
    const float* g_b   = (const float*)d_in[2];
    const float* th_w  = (const float*)d_in[3];
    const float* th_b  = (const float*)d_in[4];
    const float* ph_w  = (const float*)d_in[5];
    const float* ph_b  = (const float*)d_in[6];
    const float* W_w   = (const float*)d_in[7];
    const float* W_b   = (const float*)d_in[8];
    const float* gamma = (const float*)d_in[9];
    const float* beta  = (const float*)d_in[10];
    float* out = (float*)d_out;

    bf16 *xTh, *xTl, *wth, *wtl, *wph, *wpl, *thh, *thl, *phh, *phl;
    __half *xT16, *wg16, *W16, *g16, *E, *yT16;
    float *f, *bnsum, *bnsq;
    cudaGetSymbolAddress((void**)&xTh, g_xTh);    cudaGetSymbolAddress((void**)&xTl, g_xTl);
    cudaGetSymbolAddress((void**)&xT16, g_xT16);
    cudaGetSymbolAddress((void**)&wg16, g_wg16);
    cudaGetSymbolAddress((void**)&wth, g_wth);    cudaGetSymbolAddress((void**)&wtl, g_wtl);
    cudaGetSymbolAddress((void**)&wph, g_wph);    cudaGetSymbolAddress((void**)&wpl, g_wpl);
    cudaGetSymbolAddress((void**)&W16, g_W16);
    cudaGetSymbolAddress((void**)&g16, g_g16);
    cudaGetSymbolAddress((void**)&thh, g_thh);    cudaGetSymbolAddress((void**)&thl, g_thl);
    cudaGetSymbolAddress((void**)&phh, g_phh);    cudaGetSymbolAddress((void**)&phl, g_phl);
    cudaGetSymbolAddress((void**)&E, g_E);
    cudaGetSymbolAddress((void**)&yT16, g_yT16);
    cudaGetSymbolAddress((void**)&f, g_f);
    cudaGetSymbolAddress((void**)&bnsum, g_bnsum); cudaGetSymbolAddress((void**)&bnsq, g_bnsq);

    cudaFuncSetAttribute((const void*)proj_combo,
                         cudaFuncAttributeMaxDynamicSharedMemorySize, SM_FULL3);
    cudaFuncSetAttribute((const void*)mma_gemm<0,0,false>,
                         cudaFuncAttributeMaxDynamicSharedMemorySize, SM_FULL3);
    cudaFuncSetAttribute((const void*)mma_gemm<7,2,true>,
                         cudaFuncAttributeMaxDynamicSharedMemorySize, SM_SGL);
    cudaFuncSetAttribute((const void*)mma_gemm<3,2,true>,
                         cudaFuncAttributeMaxDynamicSharedMemorySize, SM_SGL);

    const long long sX  = (long long)C_ * T_;
    const long long sTI = (long long)T_ * I_;
    const long long sIT = (long long)I_ * T_;
    const long long sF  = (long long)T_ * T_;

    dim3 blk(256);

    // 0) combined prep: x transpose/split + weight prep + BN zero (one launch)
    prep_combo<<<16384 + 8192, blk>>>(
        x, xTh, xTl, xT16, th_w, ph_w, g_w, W_w,
        wth, wtl, wph, wpl, wg16, W16, bnsum, bnsq);

    // 1) combined: theta/phi FULL3 (1024 tiles) + g SGL (512 tiles)
    proj_combo<<<1536, blk, SM_FULL3>>>(
        xTh, xTl, wth, wtl, wph, wpl, thh, thl, phh, phl, th_b, ph_b,
        wg16, xT16, g16, g_b);

    // 2) f[t,s] = sum_i thT[t,i]*phT[s,i]  (M=T,N=T,K=I)  FULL3 -> fp32
    mma_gemm<0,0,false><<<dim3(T_ / 128, T_ / 128, B_), blk, SM_FULL3>>>(
        thh, thl, phh, phl, f, nullptr, nullptr, nullptr, nullptr, I_, T_, sTI, sTI, sF, 0);
    // 3) softmax rows -> normalized fp16 E
    softmax_f16<<<B_ * T_, blk>>>(f, E);
    // 4) yT[t,i] = sum_s E[t,s]*g[i,s]  (M=T,N=I,K=T)  SGL f16
    mma_gemm<7,2,true><<<dim3(I_ / 128, T_ / 128, B_), blk, SM_SGL>>>(
        (const bf16*)E, nullptr, (const bf16*)g16, nullptr,
        nullptr, yT16, nullptr, nullptr, nullptr, T_, I_, sF, sIT, sTI, 0);
    // 5) s[c,t] = sum_i W[c,i]*yT[t,i] + Wb[c] + x, fused BN partial sums
    mma_gemm<3,2,true><<<dim3(T_ / 128, C_ / 128, B_), blk, SM_SGL>>>(
        (const bf16*)W16, nullptr, (const bf16*)yT16, nullptr,
        out, nullptr, nullptr, W_b, x, I_, T_, 0, sTI, sX, sX);

    // 6) batchnorm apply (stats already accumulated)
    bn_apply<<<B_ * C_, blk>>>(out, bnsum, bnsq, gamma, beta);
}

// round 16
// speedup vs baseline: 1.1190x; 1.0016x over previous
#include <cuda_runtime.h>
#include <cuda_bf16.h>
#include <cuda_fp16.h>
#include <math.h>
#include <stdint.h>

#define B_ 8
#define C_ 1024
#define T_ 2048
#define I_ 512
#define BN_EPS 1e-5f

typedef __nv_bfloat16 bf16;

// ================= static scratch =================
__device__ __align__(16) bf16   g_xTh[B_ * T_ * C_];
__device__ __align__(16) bf16   g_xTl[B_ * T_ * C_];
__device__ __align__(16) __half g_xT16[B_ * T_ * C_];
__device__ __align__(16) __half g_wg16[I_ * C_];
__device__ __align__(16) bf16   g_wth[I_ * C_],  g_wtl[I_ * C_];
__device__ __align__(16) bf16   g_wph[I_ * C_],  g_wpl[I_ * C_];
__device__ __align__(16) __half g_W16[C_ * I_];
__device__ __align__(16) __half g_g16[B_ * I_ * T_];
__device__ __align__(16) bf16   g_thh[B_ * T_ * I_], g_thl[B_ * T_ * I_];
__device__ __align__(16) bf16   g_phh[B_ * T_ * I_], g_phl[B_ * T_ * I_];
__device__ __align__(16) float  g_f[33554432];            // [B,T,S] fp32
__device__ __align__(16) __half g_E[33554432];            // fp16 attention
__device__ __align__(16) __half g_yT16[B_ * T_ * I_];
__device__ float g_bnsum[C_], g_bnsq[C_];

// ================= PTX helpers (baseline features only) =================
#define LDSM4(r, a) \
    asm volatile("ldmatrix.sync.aligned.m8n8.x4.shared.b16 {%0,%1,%2,%3}, [%4];" \
        : "=r"((r)[0]), "=r"((r)[1]), "=r"((r)[2]), "=r"((r)[3]) : "r"(a))

#define MMA_BF16(c, a, b) \
    asm volatile("mma.sync.aligned.m16n8k16.row.col.f32.bf16.bf16.f32 " \
        "{%0,%1,%2,%3}, {%4,%5,%6,%7}, {%8,%9}, {%0,%1,%2,%3};" \
        : "+f"((c)[0]), "+f"((c)[1]), "+f"((c)[2]), "+f"((c)[3]) \
        : "r"((a)[0]), "r"((a)[1]), "r"((a)[2]), "r"((a)[3]), \
          "r"((b)[0]), "r"((b)[1]))

#define MMA_F16(c, a, b) \
    asm volatile("mma.sync.aligned.m16n8k16.row.col.f32.f16.f16.f32 " \
        "{%0,%1,%2,%3}, {%4,%5,%6,%7}, {%8,%9}, {%0,%1,%2,%3};" \
        : "+f"((c)[0]), "+f"((c)[1]), "+f"((c)[2]), "+f"((c)[3]) \
        : "r"((a)[0]), "r"((a)[1]), "r"((a)[2]), "r"((a)[3]), \
          "r"((b)[0]), "r"((b)[1]))

#define CP_ASYNC16(saddr, gptr) \
    asm volatile("cp.async.cg.shared.global [%0], [%1], 16;" \
        :: "r"(saddr), "l"(__cvta_generic_to_global(gptr)))
#define CP_COMMIT() asm volatile("cp.async.commit_group;" ::: "memory")

#define REDG_ADD_F32(gptr, v) \
    asm volatile("red.global.add.f32 [%0], %1;" \
        :: "l"(__cvta_generic_to_global(gptr)), "f"(v) : "memory")

#define STG_CS_V2(gptr, v0, v1) \
    asm volatile("st.global.cs.v2.f32 [%0], {%1, %2};" \
        :: "l"(__cvta_generic_to_global(gptr)), "f"(v0), "f"(v1) : "memory")

#define LDG_CS_V4(r, gptr) \
    asm volatile("ld.global.cs.v4.f32 {%0, %1, %2, %3}, [%4];" \
        : "=f"((r).x), "=f"((r).y), "=f"((r).z), "=f"((r).w) \
        : "l"(__cvta_generic_to_global(gptr)))

// ================= GEMM tile body: 128x128, K-chunk 32 ======================
// MODE 0 (FULL3): comps [Ah,Al,Bh,Bl], 3 products, 2-stage
// MODE 2 (SGL)  : comps [A,B],         1 product,  4-stage
// EPI: 0 fp32 streaming | 2 bf16 split+bias[n] | 3 fp32+bias[m]+resid+BN
//      6 f16 single+bias[m] | 7 f16 single
#define ROWB 80
#define COMPB (128 * ROWB)

template <int EPI, int MODE, bool F16>
__device__ __forceinline__ void gemm_tile(
    const bf16* __restrict__ Ah, const bf16* __restrict__ Al,
    const bf16* __restrict__ Bh, const bf16* __restrict__ Bl,
    float* __restrict__ Cf, void* __restrict__ Coh, void* __restrict__ Col,
    const float* __restrict__ bias, const float* __restrict__ resid,
    int K, int ldc, long long sA, long long sB, long long sC, long long sR,
    int bm0, int bn0, int z, char* sm)
{
    constexpr int NCOMP  = (MODE == 0) ? 4 : 2;
    constexpr int BC     = (MODE == 0) ? 2 : 1;
    constexpr int NSTAGE = (MODE == 0) ? 2 : 4;
    constexpr int BUFB = NCOMP * COMPB;
    const uint32_t sbase = (uint32_t)__cvta_generic_to_shared(sm);
    const int tid = threadIdx.x;
    const int lane = tid & 31;
    const int wid = tid >> 5;
    const int wm = (wid >> 1) * 32;
    const int wn = (wid & 1) * 64;

    const bf16* gp[NCOMP];
    gp[0] = Ah + sA * z + (long long)bm0 * K;
    if (MODE == 0) {
        gp[1] = Al + sA * z + (long long)bm0 * K;
        gp[2] = Bh + sB * z + (long long)bn0 * K;
        gp[3] = Bl + sB * z + (long long)bn0 * K;
    } else {
        gp[1] = Bh + sB * z + (long long)bn0 * K;
    }

    float acc[2][8][4];
#pragma unroll
    for (int i = 0; i < 2; i++)
#pragma unroll
        for (int j = 0; j < 8; j++)
#pragma unroll
            for (int q = 0; q < 4; q++) acc[i][j][q] = 0.0f;

    auto load_chunk = [&](int k0, int buf) {
        const uint32_t b = sbase + buf * BUFB;
#pragma unroll
        for (int i = 0; i < NCOMP * 2; i++) {
            const int u = tid + i * 256;
            const int comp = u >> 9;
            const int rem = u & 511;
            const int row = rem >> 2;
            const int un = rem & 3;
            const bf16* g = gp[comp] + (long long)row * K + k0 + un * 8;
            const uint32_t s = b + comp * COMPB + row * ROWB + un * 16;
            CP_ASYNC16(s, g);
        }
        CP_COMMIT();
    };

    auto compute = [&](int buf) {
        const uint32_t b = sbase + buf * BUFB;
        const uint32_t arow = wm + (lane & 15);
        const uint32_t akoff = ((lane >> 4) & 1) * 16;
        const uint32_t brow = wn + ((lane >> 4) << 3) + (lane & 7);
        const uint32_t bkoff = ((lane >> 3) & 1) * 16;
#pragma unroll
        for (int s = 0; s < 2; s++) {
            uint32_t ah[2][4], al[2][4];
#pragma unroll
            for (int mt = 0; mt < 2; mt++) {
                const uint32_t addr = b + (arow + mt * 16) * ROWB + s * 32 + akoff;
                LDSM4(ah[mt], addr);
                if (MODE == 0) LDSM4(al[mt], addr + COMPB);
            }
            const uint32_t bbase = b + BC * COMPB + brow * ROWB + s * 32 + bkoff;
            uint32_t rh[2][4], rl[2][4];
            LDSM4(rh[0], bbase);
            if (MODE == 0) LDSM4(rl[0], bbase + COMPB);
#pragma unroll
            for (int np = 0; np < 4; np++) {
                const int cur = np & 1;
                if (np < 3) {
                    const uint32_t na = bbase + (np + 1) * 16 * ROWB;
                    LDSM4(rh[cur ^ 1], na);
                    if (MODE == 0) LDSM4(rl[cur ^ 1], na + COMPB);
                }
                const int nb = np * 2;
                uint32_t b0[2] = { rh[cur][0], rh[cur][1] };
                uint32_t b1[2] = { rh[cur][2], rh[cur][3] };
                if (F16) {
                    MMA_F16(acc[0][nb],     ah[0], b0);
                    MMA_F16(acc[1][nb],     ah[1], b0);
                    MMA_F16(acc[0][nb + 1], ah[0], b1);
                    MMA_F16(acc[1][nb + 1], ah[1], b1);
                } else {
                    MMA_BF16(acc[0][nb],     ah[0], b0);
                    MMA_BF16(acc[1][nb],     ah[1], b0);
                    MMA_BF16(acc[0][nb + 1], ah[0], b1);
                    MMA_BF16(acc[1][nb + 1], ah[1], b1);
                }
                if (MODE == 0) {
                    uint32_t c0[2] = { rl[cur][0], rl[cur][1] };
                    uint32_t c1[2] = { rl[cur][2], rl[cur][3] };
                    MMA_BF16(acc[0][nb],     ah[0], c0);
                    MMA_BF16(acc[1][nb],     ah[1], c0);
                    MMA_BF16(acc[0][nb + 1], ah[0], c1);
                    MMA_BF16(acc[1][nb + 1], ah[1], c1);
                    MMA_BF16(acc[0][nb],     al[0], b0);
                    MMA_BF16(acc[1][nb],     al[1], b0);
                    MMA_BF16(acc[0][nb + 1], al[0], b1);
                    MMA_BF16(acc[1][nb + 1], al[1], b1);
                }
            }
        }
    };

    const int nch = K / 32;
#pragma unroll
    for (int p = 0; p < NSTAGE - 1; p++)
        load_chunk(p * 32, p);

    for (int c = 0; c < nch; c++) {
        asm volatile("cp.async.wait_group %0;" :: "n"(NSTAGE - 2) : "memory");
        __syncthreads();
        const int nxt = c + NSTAGE - 1;
        if (nxt < nch) load_chunk(nxt * 32, nxt % NSTAGE);
        compute(c % NSTAGE);
    }

    // ---- epilogue ----
    const int r0 = lane >> 2;
    const int cq = (lane & 3) * 2;
#pragma unroll
    for (int mt = 0; mt < 2; mt++) {
        const int mA = bm0 + wm + mt * 16 + r0;
        const int mB = mA + 8;
        float biasA = 0.0f, biasB = 0.0f;
        if (EPI == 3 || EPI == 6) { biasA = bias[mA]; biasB = bias[mB]; }
        const long long rowA = sC * z + (long long)mA * ldc;
        const long long rowB = sC * z + (long long)mB * ldc;
        float sA_ = 0.0f, qA_ = 0.0f, sB_ = 0.0f, qB_ = 0.0f;
#pragma unroll
        for (int nt = 0; nt < 8; nt++) {
            const int n = bn0 + wn + nt * 8 + cq;
            float v0 = acc[mt][nt][0], v1 = acc[mt][nt][1];
            float v2 = acc[mt][nt][2], v3 = acc[mt][nt][3];
            if (EPI == 2) {
                const float bn0v = bias[n], bn1v = bias[n + 1];
                v0 += bn0v; v1 += bn1v; v2 += bn0v; v3 += bn1v;
            }
            if (EPI == 3 || EPI == 6) { v0 += biasA; v1 += biasA; v2 += biasB; v3 += biasB; }
            if (EPI == 0) {
                // streaming stores: f is read exactly once later
                STG_CS_V2(Cf + rowA + n, v0, v1);
                STG_CS_V2(Cf + rowB + n, v2, v3);
            } else if (EPI == 3) {
                const long long rA = sR * z + (long long)mA * ldc + n;
                const long long rB = sR * z + (long long)mB * ldc + n;
                float2 ra = *(const float2*)(resid + rA);
                float2 rb = *(const float2*)(resid + rB);
                v0 += ra.x; v1 += ra.y; v2 += rb.x; v3 += rb.y;
                sA_ += v0 + v1;
                qA_ = fmaf(v0, v0, fmaf(v1, v1, qA_));
                sB_ += v2 + v3;
                qB_ = fmaf(v2, v2, fmaf(v3, v3, qB_));
                *(float2*)(Cf + rowA + n) = make_float2(v0, v1);
                *(float2*)(Cf + rowB + n) = make_float2(v2, v3);
            } else if (EPI == 6 || EPI == 7) {
                *(__half2*)((__half*)Coh + rowA + n) = __floats2half2_rn(v0, v1);
                *(__half2*)((__half*)Coh + rowB + n) = __floats2half2_rn(v2, v3);
            } else {
                __nv_bfloat162 hA = __floats2bfloat162_rn(v0, v1);
                __nv_bfloat162 hB = __floats2bfloat162_rn(v2, v3);
                __nv_bfloat162 lA = __floats2bfloat162_rn(
                    v0 - __bfloat162float(hA.x), v1 - __bfloat162float(hA.y));
                __nv_bfloat162 lB = __floats2bfloat162_rn(
                    v2 - __bfloat162float(hB.x), v3 - __bfloat162float(hB.y));
                *(__nv_bfloat162*)((bf16*)Coh + rowA + n) = hA;
                *(__nv_bfloat162*)((bf16*)Coh + rowB + n) = hB;
                *(__nv_bfloat162*)((bf16*)Col + rowA + n) = lA;
                *(__nv_bfloat162*)((bf16*)Col + rowB + n) = lB;
            }
        }
        if (EPI == 3) {
#pragma unroll
            for (int o = 1; o <= 2; o <<= 1) {
                sA_ += __shfl_xor_sync(~0u, sA_, o);
                qA_ += __shfl_xor_sync(~0u, qA_, o);
                sB_ += __shfl_xor_sync(~0u, sB_, o);
                qB_ += __shfl_xor_sync(~0u, qB_, o);
            }
            if ((lane & 3) == 0) {
                REDG_ADD_F32(&g_bnsum[mA], sA_);
                REDG_ADD_F32(&g_bnsq[mA],  qA_);
                REDG_ADD_F32(&g_bnsum[mB], sB_);
                REDG_ADD_F32(&g_bnsq[mB],  qB_);
            }
        }
    }
}

#define SM_FULL3 (2 * 4 * COMPB)   // 81920
#define SM_SGL   (4 * 2 * COMPB)   // 81920

// ---- plain wrapper ----
template <int EPI, int MODE, bool F16>
__global__ __launch_bounds__(256, 2)
void mma_gemm(const bf16* __restrict__ Ah, const bf16* __restrict__ Al,
              const bf16* __restrict__ Bh, const bf16* __restrict__ Bl,
              float* __restrict__ Cf, void* __restrict__ Coh, void* __restrict__ Col,
              const float* __restrict__ bias, const float* __restrict__ resid,
              int K, int ldc,
              long long sA, long long sB, long long sC, long long sR)
{
    extern __shared__ char sm[];
    gemm_tile<EPI, MODE, F16>(Ah, Al, Bh, Bl, Cf, Coh, Col, bias, resid,
                              K, ldc, sA, sB, sC, sR,
                              blockIdx.y * 128, blockIdx.x * 128, blockIdx.z, sm);
}

// ---- combined projection kernel ----
__global__ __launch_bounds__(256, 2)
void proj_combo(const bf16* __restrict__ xTh, const bf16* __restrict__ xTl,
                const bf16* __restrict__ wth, const bf16* __restrict__ wtl,
                const bf16* __restrict__ wph, const bf16* __restrict__ wpl,
                bf16* __restrict__ thh, bf16* __restrict__ thl,
                bf16* __restrict__ phh, bf16* __restrict__ phl,
                const float* __restrict__ th_b, const float* __restrict__ ph_b,
                const __half* __restrict__ wg16, const __half* __restrict__ xT16,
                __half* __restrict__ g16, const float* __restrict__ g_bias)
{
    extern __shared__ char sm[];
    const long long sXT = (long long)T_ * C_;
    const long long sTI = (long long)T_ * I_;
    const long long sIT = (long long)I_ * T_;
    const int tile = blockIdx.x;
    if (tile < 1024) {
        const int zsel = tile >> 6;
        const int rem = tile & 63;
        const int bn0 = (rem & 3) * 128;
        const int bm0 = (rem >> 2) * 128;
        const int z = zsel & 7;
        if (zsel < 8)
            gemm_tile<2, 0, false>(xTh, xTl, wth, wtl, nullptr, thh, thl, th_b,
                                   nullptr, C_, I_, sXT, 0, sTI, 0, bm0, bn0, z, sm);
        else
            gemm_tile<2, 0, false>(xTh, xTl, wph, wpl, nullptr, phh, phl, ph_b,
                                   nullptr, C_, I_, sXT, 0, sTI, 0, bm0, bn0, z, sm);
    } else {
        const int t2 = tile - 1024;
        const int bn0 = (t2 & 15) * 128;
        const int bm0 = ((t2 >> 4) & 3) * 128;
        const int z = t2 >> 6;
        gemm_tile<6, 2, true>((const bf16*)wg16, nullptr, (const bf16*)xT16, nullptr,
                              nullptr, g16, nullptr, g_bias, nullptr,
                              C_, T_, 0, sXT, sIT, 0, bm0, bn0, z, sm);
    }
}

// ================= prep combo ==============
__global__ __launch_bounds__(256)
void prep_combo(const float* __restrict__ x,
                bf16* __restrict__ xth, bf16* __restrict__ xtl, __half* __restrict__ xt16,
                const float* __restrict__ th_w, const float* __restrict__ ph_w,
                const float* __restrict__ gw,   const float* __restrict__ Ww,
                bf16* __restrict__ wth, bf16* __restrict__ wtl,
                bf16* __restrict__ wph, bf16* __restrict__ wpl,
                __half* __restrict__ wg16, __half* __restrict__ W16,
                float* __restrict__ bnsum, float* __restrict__ bnsq)
{
    const int blk = blockIdx.x;
    const int tid = threadIdx.x;
    if (blk < 16384) {
        // transpose tile 32x32: bx 0..63 (t), by 0..31 (c), bz 0..7 (b)
        __shared__ float tile[32][33];
        const int bx = blk & 63, by = (blk >> 6) & 31, b = blk >> 11;
        const int t0 = bx * 32, c0 = by * 32;
        const int tx = tid & 31, ty = tid >> 5;  // 32 x 8 load shape
        const float* xb = x + (long long)b * C_ * T_;
#pragma unroll
        for (int j = 0; j < 32; j += 8)
            tile[ty + j][tx] = xb[(long long)(c0 + ty + j) * T_ + t0 + tx];
        __syncthreads();
        // vectorized writes: thread u -> row t_local = u>>3, cols c4 = (u&7)*4
        const int t_local = tid >> 3;
        const int c4 = (tid & 7) * 4;
        float v0 = tile[c4 + 0][t_local];
        float v1 = tile[c4 + 1][t_local];
        float v2 = tile[c4 + 2][t_local];
        float v3 = tile[c4 + 3][t_local];
        const long long o = (long long)(t0 + t_local) * C_ + c0 + c4;
        bf16* thb = xth + (long long)b * T_ * C_ + o;
        bf16* tlb = xtl + (long long)b * T_ * C_ + o;
        __half* t16b = xt16 + (long long)b * T_ * C_ + o;
        __nv_bfloat162 h01 = __floats2bfloat162_rn(v0, v1);
        __nv_bfloat162 h23 = __floats2bfloat162_rn(v2, v3);
        __nv_bfloat162 l01 = __floats2bfloat162_rn(
            v0 - __bfloat162float(h01.x), v1 - __bfloat162float(h01.y));
        __nv_bfloat162 l23 = __floats2bfloat162_rn(
            v2 - __bfloat162float(h23.x), v3 - __bfloat162float(h23.y));
        __half2 f01 = __floats2half2_rn(v0, v1);
        __half2 f23 = __floats2half2_rn(v2, v3);
        *(uint2*)thb = make_uint2(*reinterpret_cast<uint32_t*>(&h01),
                                  *reinterpret_cast<uint32_t*>(&h23));
        *(uint2*)tlb = make_uint2(*reinterpret_cast<uint32_t*>(&l01),
                                  *reinterpret_cast<uint32_t*>(&l23));
        *(uint2*)t16b = make_uint2(*reinterpret_cast<uint32_t*>(&f01),
                                   *reinterpret_cast<uint32_t*>(&f23));
    } else {
        const int b2 = blk - 16384;
        const int task = b2 >> 11;
        const int i = (b2 & 2047) * 256 + tid;
        if (i >= I_ * C_) return;
        if (task == 0) {
            float v = th_w[i];
            bf16 h = __float2bfloat16(v);
            wth[i] = h;
            wtl[i] = __float2bfloat16(v - __bfloat162float(h));
            if (i < C_) { bnsum[i] = 0.0f; bnsq[i] = 0.0f; }
        } else if (task == 1) {
            float v = ph_w[i];
            bf16 h = __float2bfloat16(v);
            wph[i] = h;
            wpl[i] = __float2bfloat16(v - __bfloat162float(h));
        } else if (task == 2) {
            wg16[i] = __float2half_rn(gw[i]);
        } else {
            W16[i] = __float2half_rn(Ww[i]);
        }
    }
}

// ================= softmax (vectorized, streaming f loads) ==================
__device__ __forceinline__ float fast_exp(float x)
{
    float y = x * 1.4426950408889634f;
    float t = y + 12582912.0f;
    int e = __float_as_int(t) - 0x4B400000;
    float r = t - 12582912.0f;
    float f = y - r;
    float pq = 1.5403530393381608e-4f;
    pq = fmaf(pq, f, 1.3333558146428443e-3f);
    pq = fmaf(pq, f, 9.618129107628477e-3f);
    pq = fmaf(pq, f, 5.550410866482158e-2f);
    pq = fmaf(pq, f, 2.402265069591007e-1f);
    pq = fmaf(pq, f, 6.931471805599453e-1f);
    pq = fmaf(pq, f, 1.0f);
    float res = __int_as_float(__float_as_int(pq) + (e << 23));
    return (y > -120.0f) ? res : 0.0f;
}

__global__ __launch_bounds__(256)
void softmax_f16(const float* __restrict__ f, __half* __restrict__ E)
{
    const long long base = (long long)blockIdx.x * T_;
    const int tid = threadIdx.x;
    const int lane = tid & 31, w = tid >> 5;
    __shared__ float red[8];

    float4 a, bq;
    LDG_CS_V4(a,  f + base + tid * 8);
    LDG_CS_V4(bq, f + base + tid * 8 + 4);
    float v[8] = { a.x, a.y, a.z, a.w, bq.x, bq.y, bq.z, bq.w };

    float mx = v[0];
#pragma unroll
    for (int i = 1; i < 8; i++) mx = fmaxf(mx, v[i]);
#pragma unroll
    for (int o = 16; o; o >>= 1) mx = fmaxf(mx, __shfl_xor_sync(~0u, mx, o));
    if (lane == 0) red[w] = mx;
    __syncthreads();
    mx = red[0];
#pragma unroll
    for (int i = 1; i < 8; i++) mx = fmaxf(mx, red[i]);
    __syncthreads();

    float sum = 0.0f;
#pragma unroll
    for (int i = 0; i < 8; i++) {
        v[i] = fast_exp(v[i] - mx);
        sum += v[i];
    }
#pragma unroll
    for (int o = 16; o; o >>= 1) sum += __shfl_xor_sync(~0u, sum, o);
    if (lane == 0) red[w] = sum;
    __syncthreads();
    float tot = 0.0f;
#pragma unroll
    for (int i = 0; i < 8; i++) tot += red[i];
    const float inv = 1.0f / tot;

    __half2 h0 = __floats2half2_rn(v[0] * inv, v[1] * inv);
    __half2 h1 = __floats2half2_rn(v[2] * inv, v[3] * inv);
    __half2 h2 = __floats2half2_rn(v[4] * inv, v[5] * inv);
    __half2 h3 = __floats2half2_rn(v[6] * inv, v[7] * inv);
    uint4 pack;
    pack.x = *reinterpret_cast<uint32_t*>(&h0);
    pack.y = *reinterpret_cast<uint32_t*>(&h1);
    pack.z = *reinterpret_cast<uint32_t*>(&h2);
    pack.w = *reinterpret_cast<uint32_t*>(&h3);
    *(uint4*)(E + base + tid * 8) = pack;
}

// ================= batchnorm apply =================
__global__ __launch_bounds__(256)
void bn_apply(float* __restrict__ s, const float* __restrict__ bnsum,
              const float* __restrict__ bnsq, const float* __restrict__ gamma,
              const float* __restrict__ beta)
{
    const int blk = blockIdx.x;             // B_*C_/2 blocks, 2 rows each
    const int half = threadIdx.x >> 7;      // 0..1: which row
    const int tid = threadIdx.x & 127;
    const int bc = blk * 2 + half;
    const int c = bc & (C_ - 1);
    const long long base = (long long)bc * T_;
    const float inv_n = 1.0f / (float)(B_ * T_);
    const float m = bnsum[c] * inv_n;
    const float var = bnsq[c] * inv_n - m * m;
    const float r = rsqrtf(var + BN_EPS);
    const float g = gamma[c], be = beta[c];
#pragma unroll
    for (int i = 0; i < 4; i++) {
        float4* p = (float4*)(s + base + (tid + i * 128) * 4);
        float4 v = *p;
        v.x = fmaf((v.x - m) * r, g, be);
        v.y = fmaf((v.y - m) * r, g, be);
        v.z = fmaf((v.z - m) * r, g, be);
        v.w = fmaf((v.w - m) * r, g, be);
        *p = v;
    }
}

// ================= launcher =================
extern "C" void kernel_launch(void* const* d_in, const int* in_sizes, int n_in,
                              void* d_out, int out_size)
{
    const float* x     = (const float*)d_in[0];
    const float* g_w   = (const float*)d_in[1];
    const float* g_b   = (const float*)d_in[2];
    const float* th_w  = (const float*)d_in[3];
    const float* th_b  = (const float*)d_in[4];
    const float* ph_w  = (const float*)d_in[5];
    const float* ph_b  = (const float*)d_in[6];
    const float* W_w   = (const float*)d_in[7];
    const float* W_b   = (const float*)d_in[8];
    const float* gamma = (const float*)d_in[9];
    const float* beta  = (const float*)d_in[10];
    float* out = (float*)d_out;

    bf16 *xTh, *xTl, *wth, *wtl, *wph, *wpl, *thh, *thl, *phh, *phl;
    __half *xT16, *wg16, *W16, *g16, *E, *yT16;
    float *f, *bnsum, *bnsq;
    cudaGetSymbolAddress((void**)&xTh, g_xTh);    cudaGetSymbolAddress((void**)&xTl, g_xTl);
    cudaGetSymbolAddress((void**)&xT16, g_xT16);
    cudaGetSymbolAddress((void**)&wg16, g_wg16);
    cudaGetSymbolAddress((void**)&wth, g_wth);    cudaGetSymbolAddress((void**)&wtl, g_wtl);
    cudaGetSymbolAddress((void**)&wph, g_wph);    cudaGetSymbolAddress((void**)&wpl, g_wpl);
    cudaGetSymbolAddress((void**)&W16, g_W16);
    cudaGetSymbolAddress((void**)&g16, g_g16);
    cudaGetSymbolAddress((void**)&thh, g_thh);    cudaGetSymbolAddress((void**)&thl, g_thl);
    cudaGetSymbolAddress((void**)&phh, g_phh);    cudaGetSymbolAddress((void**)&phl, g_phl);
    cudaGetSymbolAddress((void**)&E, g_E);
    cudaGetSymbolAddress((void**)&yT16, g_yT16);
    cudaGetSymbolAddress((void**)&f, g_f);
    cudaGetSymbolAddress((void**)&bnsum, g_bnsum); cudaGetSymbolAddress((void**)&bnsq, g_bnsq);

    cudaFuncSetAttribute((const void*)proj_combo,
                         cudaFuncAttributeMaxDynamicSharedMemorySize, SM_FULL3);
    cudaFuncSetAttribute((const void*)mma_gemm<0,0,false>,
                         cudaFuncAttributeMaxDynamicSharedMemorySize, SM_FULL3);
    cudaFuncSetAttribute((const void*)mma_gemm<7,2,true>,
                         cudaFuncAttributeMaxDynamicSharedMemorySize, SM_SGL);
    cudaFuncSetAttribute((const void*)mma_gemm<3,2,true>,
                         cudaFuncAttributeMaxDynamicSharedMemorySize, SM_SGL);

    const long long sX  = (long long)C_ * T_;
    const long long sTI = (long long)T_ * I_;
    const long long sIT = (long long)I_ * T_;
    const long long sF  = (long long)T_ * T_;

    dim3 blk(256);

    // 0) combined prep: x transpose/split + weight prep + BN zero
    prep_combo<<<16384 + 8192, blk>>>(
        x, xTh, xTl, xT16, th_w, ph_w, g_w, W_w,
        wth, wtl, wph, wpl, wg16, W16, bnsum, bnsq);

    // 1) combined: theta/phi FULL3 (1024 tiles) + g SGL (512 tiles)
    proj_combo<<<1536, blk, SM_FULL3>>>(
        xTh, xTl, wth, wtl, wph, wpl, thh, thl, phh, phl, th_b, ph_b,
        wg16, xT16, g16, g_b);

    // 2) f[t,s] = sum_i thT[t,i]*phT[s,i]  (M=T,N=T,K=I)  FULL3 -> fp32 (.cs)
    mma_gemm<0,0,false><<<dim3(T_ / 128, T_ / 128, B_), blk, SM_FULL3>>>(
        thh, thl, phh, phl, f, nullptr, nullptr, nullptr, nullptr, I_, T_, sTI, sTI, sF, 0);
    // 3) softmax rows -> normalized fp16 E
    softmax_f16<<<B_ * T_, blk>>>(f, E);
    // 4) yT[t,i] = sum_s E[t,s]*g[i,s]  (M=T,N=I,K=T)  SGL f16
    mma_gemm<7,2,true><<<dim3(I_ / 128, T_ / 128, B_), blk, SM_SGL>>>(
        (const bf16*)E, nullptr, (const bf16*)g16, nullptr,
        nullptr, yT16, nullptr, nullptr, nullptr, T_, I_, sF, sIT, sTI, 0);
    // 5) s[c,t] = sum_i W[c,i]*yT[t,i] + Wb[c] + x, fused BN partial sums
    mma_gemm<3,2,true><<<dim3(T_ / 128, C_ / 128, B_), blk, SM_SGL>>>(
        (const bf16*)W16, nullptr, (const bf16*)yT16, nullptr,
        out, nullptr, nullptr, W_b, x, I_, T_, 0, sTI, sX, sX);

    // 6) batchnorm apply
    bn_apply<<<B_ * C_ / 2, blk>>>(out, bnsum, bnsq, gamma, beta);
}